// round 9
// baseline (speedup 1.0000x reference)
#include <cuda_runtime.h>
#include <cuda_bf16.h>
#include <math.h>
#include <stdint.h>

// ---------------------------------------------------------------------------
// TransformerBlock B=8 S=1024 D=1024 H=16 DH=64 F=4096 (fp32 in/out)
// All matmuls on mma.sync.m16n8k16 bf16 (x3 hi/lo split, fp32 accum).
// GEMM: BM=128 BN=256 BK=64, 2-stage cp.async pipeline, ONE sync per k-tile.
// ---------------------------------------------------------------------------

#define Bb 8
#define Ss 1024
#define Dd 1024
#define Hh 16
#define DH 64
#define Ff 4096
#define TT (Bb*Ss)

typedef __nv_bfloat16 bf16;

// ------------------------- static device scratch ---------------------------
__device__ float g_sa[TT*Dd];
__device__ float g_h [TT*Dd];
__device__ float g_f2[TT*Dd];
__device__ float g_mf[Bb*Ss];

__device__ bf16 g_xh [TT*Dd],  g_xl [TT*Dd];
__device__ bf16 g_qh [TT*Dd],  g_ql [TT*Dd];
__device__ bf16 g_kh [TT*Dd],  g_kl [TT*Dd];
__device__ bf16 g_vh [TT*Dd],  g_vl [TT*Dd];
__device__ bf16 g_cxh[TT*Dd],  g_cxl[TT*Dd];
__device__ bf16 g_hh [TT*Dd],  g_hl [TT*Dd];
__device__ bf16 g_fh [TT*Ff],  g_fl [TT*Ff];
__device__ bf16 g_wqh[Dd*Dd],  g_wql[Dd*Dd];
__device__ bf16 g_wkh[Dd*Dd],  g_wkl[Dd*Dd];
__device__ bf16 g_wvh[Dd*Dd],  g_wvl[Dd*Dd];
__device__ bf16 g_woh[Dd*Dd],  g_wol[Dd*Dd];
__device__ bf16 g_w1h[Ff*Dd],  g_w1l[Ff*Dd];
__device__ bf16 g_w2h[Dd*Ff],  g_w2l[Dd*Ff];

// pointer table for batched weight conversion
__device__ const float* g_cvt_src[4];
__device__ bf16*        g_cvt_dh [4];
__device__ bf16*        g_cvt_dl [4];

// ------------------------------ helpers ------------------------------------
__device__ __forceinline__ uint32_t smem_u32(const void* p) {
    uint32_t a;
    asm("{ .reg .u64 t; cvta.to.shared.u64 t, %1; cvt.u32.u64 %0, t; }"
        : "=r"(a) : "l"(p));
    return a;
}
__device__ __forceinline__ void cp16(uint32_t s, const void* g) {
    asm volatile("cp.async.cg.shared.global [%0], [%1], 16;" :: "r"(s), "l"(g));
}
#define CP_COMMIT() asm volatile("cp.async.commit_group;" ::: "memory")
#define CP_WAIT0()  asm volatile("cp.async.wait_group 0;" ::: "memory")

#define SWZ(x)   ((x) ^ (((x) >> 3) & 0x70))   // 128B rows

__device__ __forceinline__ void ldsm4(uint32_t* r, uint32_t a) {
    asm volatile("ldmatrix.sync.aligned.m8n8.x4.shared.b16 {%0,%1,%2,%3}, [%4];"
        : "=r"(r[0]), "=r"(r[1]), "=r"(r[2]), "=r"(r[3]) : "r"(a));
}
__device__ __forceinline__ void ldsm4t(uint32_t* r, uint32_t a) {
    asm volatile("ldmatrix.sync.aligned.m8n8.x4.trans.shared.b16 {%0,%1,%2,%3}, [%4];"
        : "=r"(r[0]), "=r"(r[1]), "=r"(r[2]), "=r"(r[3]) : "r"(a));
}
__device__ __forceinline__ void mma_bf16(float* d, const uint32_t* a, const uint32_t* b) {
    asm volatile(
        "mma.sync.aligned.m16n8k16.row.col.f32.bf16.bf16.f32 "
        "{%0,%1,%2,%3}, {%4,%5,%6,%7}, {%8,%9}, {%0,%1,%2,%3};"
        : "+f"(d[0]), "+f"(d[1]), "+f"(d[2]), "+f"(d[3])
        : "r"(a[0]), "r"(a[1]), "r"(a[2]), "r"(a[3]), "r"(b[0]), "r"(b[1]));
}
__device__ __forceinline__ uint32_t packbf(float a, float b) {
    __nv_bfloat162 t = __floats2bfloat162_rn(a, b);
    return reinterpret_cast<uint32_t&>(t);
}
__device__ __forceinline__ float gelu_exact(float v) {
    return 0.5f * v * (1.0f + erff(v * 0.70710678118654752440f));
}

// ----------------------------- GEMM core -----------------------------------
#define GSTG 98304                 // per stage: A(h,l) 32K + B(h,l) 64K
#define GEMM_SMEM (2*GSTG)

#define EPI_HEADS 0
#define EPI_RES   1
#define EPI_GELU  2

// shared mainloop: accumulates C tile for (m0,n0) over K.
// ONE __syncthreads per k-tile:
//   wait(all)  -> stage kt data complete (this thread)
//   sync       -> data visible to all warps AND all warps finished stage kt-1
//   issue kt+1 -> overwrites buffer of stage kt-1 (protected by the sync)
//   compute kt
template<typename ACC>
__device__ __forceinline__ void gemm_mainloop(
    uint32_t sb, int tid, int lane, int wr, int wc,
    const bf16* A_h, const bf16* A_l, const bf16* W_h, const bf16* W_l,
    int m0, int n0, int K, ACC& acc)
{
    auto load_stage = [&](int st, int kt) {
        const uint32_t s0 = sb + st * GSTG;
        const int k0 = kt * 64;
#pragma unroll
        for (int t = 0; t < 4; t++) {
            int idx = t * 256 + tid;
            int row = idx >> 3, c = idx & 7;
            uint32_t off = SWZ((uint32_t)(row * 128 + c * 16));
            size_t go = (size_t)(m0 + row) * K + k0 + c * 8;
            cp16(s0 + off,         A_h + go);
            cp16(s0 + 16384 + off, A_l + go);
        }
#pragma unroll
        for (int t = 0; t < 8; t++) {
            int idx = t * 256 + tid;
            int row = idx >> 3, c = idx & 7;
            uint32_t off = SWZ((uint32_t)(row * 128 + c * 16));
            size_t go = (size_t)(n0 + row) * K + k0 + c * 8;
            cp16(s0 + 32768 + off, W_h + go);
            cp16(s0 + 65536 + off, W_l + go);
        }
    };

    const int KT = K >> 6;
    load_stage(0, 0);
    CP_COMMIT();

    const int lr16 = lane & 15;
    const int alc  = (lane >> 4) * 16;
    const int brow = wc * 64 + (lane & 7) + ((lane >> 4) & 1) * 8;
    const int bcol = ((lane >> 3) & 1) * 16;

    for (int kt = 0; kt < KT; kt++) {
        CP_WAIT0();                 // only group kt outstanding here
        __syncthreads();
        if (kt + 1 < KT) { load_stage((kt + 1) & 1, kt + 1); CP_COMMIT(); }

        const uint32_t sA  = sb + (kt & 1) * GSTG;
        const uint32_t sAl = sA + 16384;
        const uint32_t sB  = sA + 32768;
        const uint32_t sBl = sA + 65536;

#pragma unroll
        for (int ks = 0; ks < 4; ks++) {
            uint32_t ah[4][4], al[4][4];
#pragma unroll
            for (int i = 0; i < 4; i++) {
                uint32_t off = SWZ((uint32_t)((wr * 64 + i * 16 + lr16) * 128 + ks * 32 + alc));
                ldsm4(ah[i], sA  + off);
                ldsm4(al[i], sAl + off);
            }
#pragma unroll
            for (int p = 0; p < 4; p++) {
                uint32_t boff = SWZ((uint32_t)((brow + p * 16) * 128 + ks * 32 + bcol));
                uint32_t bh[4], bl[4];
                ldsm4(bh, sB  + boff);
                ldsm4(bl, sBl + boff);
#pragma unroll
                for (int a = 0; a < 2; a++) {
#pragma unroll
                    for (int i = 0; i < 4; i++) {
                        mma_bf16(acc[i][p * 2 + a], ah[i], &bh[2 * a]);
                        mma_bf16(acc[i][p * 2 + a], ah[i], &bl[2 * a]);
                        mma_bf16(acc[i][p * 2 + a], al[i], &bh[2 * a]);
                    }
                }
            }
        }
    }
}

// fused QKV projection: grid (12, 64); blockIdx.x>>2 selects Q/K/V
__global__ void __launch_bounds__(256) gemm_qkv(
    const bf16* __restrict__ xh, const bf16* __restrict__ xl,
    const bf16* __restrict__ wqh, const bf16* __restrict__ wql,
    const bf16* __restrict__ wkh, const bf16* __restrict__ wkl,
    const bf16* __restrict__ wvh, const bf16* __restrict__ wvl,
    const float* __restrict__ bq, const float* __restrict__ bk,
    const float* __restrict__ bv,
    bf16* __restrict__ qh, bf16* __restrict__ ql,
    bf16* __restrict__ kh, bf16* __restrict__ kl,
    bf16* __restrict__ vh, bf16* __restrict__ vl)
{
    extern __shared__ char smem[];
    const uint32_t sb = smem_u32(smem);
    const int tid = threadIdx.x;
    const int lane = tid & 31, wid = tid >> 5;
    const int wr = wid >> 2, wc = wid & 3;
    const int mat = blockIdx.x >> 2;
    const int n0 = (blockIdx.x & 3) * 256;
    const int m0 = blockIdx.y * 128;

    const bf16* W_h = (mat == 0) ? wqh : (mat == 1) ? wkh : wvh;
    const bf16* W_l = (mat == 0) ? wql : (mat == 1) ? wkl : wvl;
    const float* bias = (mat == 0) ? bq : (mat == 1) ? bk : bv;
    bf16* Ch = (mat == 0) ? qh : (mat == 1) ? kh : vh;
    bf16* Cl = (mat == 0) ? ql : (mat == 1) ? kl : vl;
    const float scale = (mat == 0) ? 0.125f : 1.0f;

    float acc[4][8][4];
#pragma unroll
    for (int i = 0; i < 4; i++)
#pragma unroll
        for (int j = 0; j < 8; j++)
#pragma unroll
            for (int e = 0; e < 4; e++) acc[i][j][e] = 0.f;

    gemm_mainloop(sb, tid, lane, wr, wc, xh, xl, W_h, W_l, m0, n0, Dd, acc);

#pragma unroll
    for (int i = 0; i < 4; i++) {
        const int r0 = m0 + wr * 64 + i * 16 + (lane >> 2);
#pragma unroll
        for (int j = 0; j < 8; j++) {
            const int n = n0 + wc * 64 + j * 8 + 2 * (lane & 3);
            const float2 b2 = *(const float2*)&bias[n];
#pragma unroll
            for (int hf = 0; hf < 2; hf++) {
                const int m = r0 + hf * 8;
                float v0 = (acc[i][j][hf * 2 + 0] + b2.x) * scale;
                float v1 = (acc[i][j][hf * 2 + 1] + b2.y) * scale;
                const size_t o = (((size_t)(m >> 10) * Hh + (n >> 6)) * Ss + (m & 1023)) * DH + (n & 63);
                const float h0 = __bfloat162float(__float2bfloat16(v0));
                const float h1 = __bfloat162float(__float2bfloat16(v1));
                *(uint32_t*)(Ch + o) = packbf(h0, h1);
                *(uint32_t*)(Cl + o) = packbf(v0 - h0, v1 - h1);
            }
        }
    }
}

template<int EPI>
__global__ void __launch_bounds__(256) gemm_mma(
    const bf16* __restrict__ A_h, const bf16* __restrict__ A_l,
    const bf16* __restrict__ W_h, const bf16* __restrict__ W_l,
    const float* __restrict__ bias, const float* __restrict__ res,
    float* __restrict__ Cf, bf16* __restrict__ Ch, bf16* __restrict__ Cl,
    int N, int K)
{
    extern __shared__ char smem[];
    const uint32_t sb = smem_u32(smem);
    const int tid = threadIdx.x;
    const int lane = tid & 31, wid = tid >> 5;
    const int wr = wid >> 2, wc = wid & 3;
    const int m0 = blockIdx.y * 128, n0 = blockIdx.x * 256;

    float acc[4][8][4];
#pragma unroll
    for (int i = 0; i < 4; i++)
#pragma unroll
        for (int j = 0; j < 8; j++)
#pragma unroll
            for (int e = 0; e < 4; e++) acc[i][j][e] = 0.f;

    gemm_mainloop(sb, tid, lane, wr, wc, A_h, A_l, W_h, W_l, m0, n0, K, acc);

#pragma unroll
    for (int i = 0; i < 4; i++) {
        const int r0 = m0 + wr * 64 + i * 16 + (lane >> 2);
#pragma unroll
        for (int j = 0; j < 8; j++) {
            const int n = n0 + wc * 64 + j * 8 + 2 * (lane & 3);
            const float2 b2 = *(const float2*)&bias[n];
#pragma unroll
            for (int hf = 0; hf < 2; hf++) {
                const int m = r0 + hf * 8;
                float v0 = acc[i][j][hf * 2 + 0] + b2.x;
                float v1 = acc[i][j][hf * 2 + 1] + b2.y;
                if (EPI == EPI_RES) {
                    const size_t o = (size_t)m * N + n;
                    const float2 rr = *(const float2*)&res[o];
                    float2 w; w.x = v0 + rr.x; w.y = v1 + rr.y;
                    *(float2*)&Cf[o] = w;
                } else { // EPI_GELU -> bf16 hi/lo
                    const size_t o = (size_t)m * N + n;
                    const float g0 = gelu_exact(v0), g1 = gelu_exact(v1);
                    const float h0 = __bfloat162float(__float2bfloat16(g0));
                    const float h1 = __bfloat162float(__float2bfloat16(g1));
                    *(uint32_t*)(Ch + o) = packbf(h0, h1);
                    *(uint32_t*)(Cl + o) = packbf(g0 - h0, g1 - h1);
                }
            }
        }
    }
}

// --------------------------- flash attention (mma) --------------------------
#define ATT_Q   0
#define ATT_ST  32768
#define ATT_STG 65536
#define ATT_MSK (ATT_ST + 2*ATT_STG)
#define ATT_SMEM (ATT_MSK + 1024)

__global__ void __launch_bounds__(256) attn_mma(
    const bf16* __restrict__ qh, const bf16* __restrict__ ql,
    const bf16* __restrict__ kh, const bf16* __restrict__ kl,
    const bf16* __restrict__ vh, const bf16* __restrict__ vl,
    const float* __restrict__ mf,
    bf16* __restrict__ oh, bf16* __restrict__ ol)
{
    extern __shared__ char smem[];
    const uint32_t sb = smem_u32(smem);
    const int tid = threadIdx.x;
    const int lane = tid & 31, wid = tid >> 5;
    const int b = blockIdx.z, h = blockIdx.y, q0 = blockIdx.x * 128;

    const size_t bh_off = ((size_t)(b * Hh + h) * Ss) * DH;
    const bf16* qhp = qh + bh_off + (size_t)q0 * DH;
    const bf16* qlp = ql + bh_off + (size_t)q0 * DH;
    const bf16* khp = kh + bh_off;
    const bf16* klp = kl + bh_off;
    const bf16* vhp = vh + bh_off;
    const bf16* vlp = vl + bh_off;
    const float* mfb = mf + b * Ss;

    auto load_kv = [&](int st, int kt) {
        const uint32_t s0 = sb + ATT_ST + st * ATT_STG;
        const int kv0 = kt * 128;
#pragma unroll
        for (int t = 0; t < 4; t++) {
            int idx = t * 256 + tid;
            int row = idx >> 3, c = idx & 7;
            uint32_t off = SWZ((uint32_t)(row * 128 + c * 16));
            size_t go = (size_t)(kv0 + row) * DH + c * 8;
            cp16(s0 + off,         khp + go);
            cp16(s0 + 16384 + off, klp + go);
            cp16(s0 + 32768 + off, vhp + go);
            cp16(s0 + 49152 + off, vlp + go);
        }
        if (tid < 32) cp16(sb + ATT_MSK + st * 512 + tid * 16, mfb + kv0 + tid * 4);
    };

    {
#pragma unroll
        for (int t = 0; t < 4; t++) {
            int idx = t * 256 + tid;
            int row = idx >> 3, c = idx & 7;
            uint32_t off = SWZ((uint32_t)(row * 128 + c * 16));
            size_t go = (size_t)row * DH + c * 8;
            cp16(sb + ATT_Q + off,         qhp + go);
            cp16(sb + ATT_Q + 16384 + off, qlp + go);
        }
        load_kv(0, 0);
        CP_COMMIT();
    }

    uint32_t qfh[4][4], qfl[4][4];
    float oacc[8][4];
#pragma unroll
    for (int q = 0; q < 8; q++)
#pragma unroll
        for (int e = 0; e < 4; e++) oacc[q][e] = 0.f;
    float mrow0 = -INFINITY, mrow1 = -INFINITY, lsum0 = 0.f, lsum1 = 0.f;

    const int lr16 = lane & 15;
    const int alc  = (lane >> 4) * 16;
    const int brow = (lane & 7) + ((lane >> 4) & 1) * 8;
    const int bcol = ((lane >> 3) & 1) * 16;
    const int vrow = (lane & 7) + ((lane >> 3) & 1) * 8;
    const int vcol = (lane >> 4) * 16;

    const int NKV = Ss / 128;
    for (int kt = 0; kt < NKV; kt++) {
        CP_WAIT0();                 // stage kt (and Q on kt==0) complete
        __syncthreads();            // visible to all; all warps done stage kt-1
        if (kt + 1 < NKV) { load_kv((kt + 1) & 1, kt + 1); CP_COMMIT(); }

        if (kt == 0) {
#pragma unroll
            for (int ks = 0; ks < 4; ks++) {
                uint32_t off = SWZ((uint32_t)((wid * 16 + lr16) * 128 + ks * 32 + alc));
                ldsm4(qfh[ks], sb + ATT_Q + off);
                ldsm4(qfl[ks], sb + ATT_Q + 16384 + off);
            }
        }

        const uint32_t sK  = sb + ATT_ST + (kt & 1) * ATT_STG;
        const uint32_t sKl = sK + 16384;
        const uint32_t sV  = sK + 32768;
        const uint32_t sVl = sK + 49152;
        const uint32_t sM  = sb + ATT_MSK + (kt & 1) * 512;

        float sacc[16][4];
#pragma unroll
        for (int j = 0; j < 16; j++)
#pragma unroll
            for (int e = 0; e < 4; e++) sacc[j][e] = 0.f;

#pragma unroll
        for (int p = 0; p < 8; p++) {
#pragma unroll
            for (int ks = 0; ks < 4; ks++) {
                uint32_t koff = SWZ((uint32_t)((p * 16 + brow) * 128 + ks * 32 + bcol));
                uint32_t kbh[4], kbl[4];
                ldsm4(kbh, sK  + koff);
                ldsm4(kbl, sKl + koff);
#pragma unroll
                for (int a = 0; a < 2; a++) {
                    mma_bf16(sacc[p * 2 + a], qfh[ks], &kbh[2 * a]);
                    mma_bf16(sacc[p * 2 + a], qfh[ks], &kbl[2 * a]);
                    mma_bf16(sacc[p * 2 + a], qfl[ks], &kbh[2 * a]);
                }
            }
        }

        float mx0 = -INFINITY, mx1 = -INFINITY;
#pragma unroll
        for (int j = 0; j < 16; j++) {
            mx0 = fmaxf(mx0, fmaxf(sacc[j][0], sacc[j][1]));
            mx1 = fmaxf(mx1, fmaxf(sacc[j][2], sacc[j][3]));
        }
        mx0 = fmaxf(mx0, __shfl_xor_sync(0xffffffffu, mx0, 1));
        mx0 = fmaxf(mx0, __shfl_xor_sync(0xffffffffu, mx0, 2));
        mx1 = fmaxf(mx1, __shfl_xor_sync(0xffffffffu, mx1, 1));
        mx1 = fmaxf(mx1, __shfl_xor_sync(0xffffffffu, mx1, 2));
        const float mnew0 = fmaxf(mrow0, mx0);
        const float mnew1 = fmaxf(mrow1, mx1);
        const float al0 = __expf(mrow0 - mnew0);
        const float al1 = __expf(mrow1 - mnew1);
        float ls0 = 0.f, ls1 = 0.f;
#pragma unroll
        for (int j = 0; j < 16; j++) {
            float2 mv;
            asm volatile("ld.shared.v2.f32 {%0,%1}, [%2];"
                : "=f"(mv.x), "=f"(mv.y)
                : "r"(sM + (uint32_t)((j * 8 + 2 * (lane & 3)) * 4)));
            float p0 = __expf(sacc[j][0] - mnew0) * mv.x;
            float p1 = __expf(sacc[j][1] - mnew0) * mv.y;
            float p2 = __expf(sacc[j][2] - mnew1) * mv.x;
            float p3 = __expf(sacc[j][3] - mnew1) * mv.y;
            sacc[j][0] = p0; sacc[j][1] = p1; sacc[j][2] = p2; sacc[j][3] = p3;
            ls0 += p0 + p1; ls1 += p2 + p3;
        }
        ls0 += __shfl_xor_sync(0xffffffffu, ls0, 1);
        ls0 += __shfl_xor_sync(0xffffffffu, ls0, 2);
        ls1 += __shfl_xor_sync(0xffffffffu, ls1, 1);
        ls1 += __shfl_xor_sync(0xffffffffu, ls1, 2);
        lsum0 = lsum0 * al0 + ls0;
        lsum1 = lsum1 * al1 + ls1;
        mrow0 = mnew0; mrow1 = mnew1;
#pragma unroll
        for (int q = 0; q < 8; q++) {
            oacc[q][0] *= al0; oacc[q][1] *= al0;
            oacc[q][2] *= al1; oacc[q][3] *= al1;
        }

#pragma unroll
        for (int ks = 0; ks < 8; ks++) {
            uint32_t ph[4], pl[4];
            {
                const float* s0 = sacc[2 * ks];
                const float* s1 = sacc[2 * ks + 1];
                float h00 = __bfloat162float(__float2bfloat16(s0[0]));
                float h01 = __bfloat162float(__float2bfloat16(s0[1]));
                float h02 = __bfloat162float(__float2bfloat16(s0[2]));
                float h03 = __bfloat162float(__float2bfloat16(s0[3]));
                float h10 = __bfloat162float(__float2bfloat16(s1[0]));
                float h11 = __bfloat162float(__float2bfloat16(s1[1]));
                float h12 = __bfloat162float(__float2bfloat16(s1[2]));
                float h13 = __bfloat162float(__float2bfloat16(s1[3]));
                ph[0] = packbf(h00, h01); ph[1] = packbf(h02, h03);
                ph[2] = packbf(h10, h11); ph[3] = packbf(h12, h13);
                pl[0] = packbf(s0[0] - h00, s0[1] - h01);
                pl[1] = packbf(s0[2] - h02, s0[3] - h03);
                pl[2] = packbf(s1[0] - h10, s1[1] - h11);
                pl[3] = packbf(s1[2] - h12, s1[3] - h13);
            }
#pragma unroll
            for (int q = 0; q < 4; q++) {
                uint32_t voff = SWZ((uint32_t)((ks * 16 + vrow) * 128 + q * 32 + vcol));
                uint32_t vbh[4], vbl[4];
                ldsm4t(vbh, sV  + voff);
                ldsm4t(vbl, sVl + voff);
#pragma unroll
                for (int a = 0; a < 2; a++) {
                    mma_bf16(oacc[q * 2 + a], ph, &vbh[2 * a]);
                    mma_bf16(oacc[q * 2 + a], ph, &vbl[2 * a]);
                    mma_bf16(oacc[q * 2 + a], pl, &vbh[2 * a]);
                }
            }
        }
    }

    const float inv0 = 1.f / lsum0;
    const float inv1 = 1.f / lsum1;
    const int tok0 = b * Ss + q0 + wid * 16 + (lane >> 2);
#pragma unroll
    for (int q = 0; q < 8; q++) {
        const int col = h * DH + q * 8 + 2 * (lane & 3);
        {
            float v0 = oacc[q][0] * inv0, v1 = oacc[q][1] * inv0;
            const size_t o = (size_t)tok0 * Dd + col;
            float h0 = __bfloat162float(__float2bfloat16(v0));
            float h1 = __bfloat162float(__float2bfloat16(v1));
            *(uint32_t*)(oh + o) = packbf(h0, h1);
            *(uint32_t*)(ol + o) = packbf(v0 - h0, v1 - h1);
        }
        {
            float v0 = oacc[q][2] * inv1, v1 = oacc[q][3] * inv1;
            const size_t o = (size_t)(tok0 + 8) * Dd + col;
            float h0 = __bfloat162float(__float2bfloat16(v0));
            float h1 = __bfloat162float(__float2bfloat16(v1));
            *(uint32_t*)(oh + o) = packbf(h0, h1);
            *(uint32_t*)(ol + o) = packbf(v0 - h0, v1 - h1);
        }
    }
}

// ------------------------------ LayerNorm -----------------------------------
template<bool WB>
__global__ void __launch_bounds__(256) ln_k(
    const float* __restrict__ X, const float* __restrict__ gg,
    const float* __restrict__ bb, float* __restrict__ Y,
    bf16* __restrict__ Yh, bf16* __restrict__ Yl)
{
    __shared__ float red[16];
    const int row = blockIdx.x, tid = threadIdx.x;
    const float4 x = ((const float4*)(X + (size_t)row * Dd))[tid];
    float s  = x.x + x.y + x.z + x.w;
    float s2 = x.x*x.x + x.y*x.y + x.z*x.z + x.w*x.w;
#pragma unroll
    for (int o = 16; o; o >>= 1) {
        s  += __shfl_xor_sync(0xffffffffu, s,  o);
        s2 += __shfl_xor_sync(0xffffffffu, s2, o);
    }
    const int w = tid >> 5, lane = tid & 31;
    if (lane == 0) { red[w] = s; red[8 + w] = s2; }
    __syncthreads();
    if (tid < 32) {
        float a = (tid < 8) ? red[tid]     : 0.f;
        float c = (tid < 8) ? red[8 + tid] : 0.f;
#pragma unroll
        for (int o = 4; o; o >>= 1) {
            a += __shfl_xor_sync(0xffffffffu, a, o);
            c += __shfl_xor_sync(0xffffffffu, c, o);
        }
        if (tid == 0) { red[0] = a; red[8] = c; }
    }
    __syncthreads();
    const float mean = red[0] * (1.f / Dd);
    const float var  = red[8] * (1.f / Dd) - mean * mean;
    const float rstd = rsqrtf(var + 1e-12f);
    const float4 gv = ((const float4*)gg)[tid];
    const float4 bv = ((const float4*)bb)[tid];
    float4 y;
    y.x = (x.x - mean) * rstd * gv.x + bv.x;
    y.y = (x.y - mean) * rstd * gv.y + bv.y;
    y.z = (x.z - mean) * rstd * gv.z + bv.z;
    y.w = (x.w - mean) * rstd * gv.w + bv.w;
    ((float4*)(Y + (size_t)row * Dd))[tid] = y;
    if (WB) {
        float h0 = __bfloat162float(__float2bfloat16(y.x));
        float h1 = __bfloat162float(__float2bfloat16(y.y));
        float h2 = __bfloat162float(__float2bfloat16(y.z));
        float h3 = __bfloat162float(__float2bfloat16(y.w));
        uint2 vh2, vl2;
        vh2.x = packbf(h0, h1);         vh2.y = packbf(h2, h3);
        vl2.x = packbf(y.x - h0, y.y - h1); vl2.y = packbf(y.z - h2, y.w - h3);
        ((uint2*)(Yh + (size_t)row * Dd))[tid] = vh2;
        ((uint2*)(Yl + (size_t)row * Dd))[tid] = vl2;
    }
}

// -------------------------- fp32 -> bf16 hi/lo ------------------------------
__device__ __forceinline__ void cvt_body(const float* __restrict__ X,
                                         bf16* __restrict__ Hc,
                                         bf16* __restrict__ Lc, int i)
{
    float4 v = ((const float4*)X)[i];
    float h0 = __bfloat162float(__float2bfloat16(v.x));
    float h1 = __bfloat162float(__float2bfloat16(v.y));
    float h2 = __bfloat162float(__float2bfloat16(v.z));
    float h3 = __bfloat162float(__float2bfloat16(v.w));
    uint2 vh2, vl2;
    vh2.x = packbf(h0, h1);          vh2.y = packbf(h2, h3);
    vl2.x = packbf(v.x - h0, v.y - h1); vl2.y = packbf(v.z - h2, v.w - h3);
    ((uint2*)Hc)[i] = vh2;
    ((uint2*)Lc)[i] = vl2;
}

__global__ void __launch_bounds__(256) cvt_k(
    const float* __restrict__ X, bf16* __restrict__ Hc,
    bf16* __restrict__ Lc, int n4)
{
    int i = blockIdx.x * 256 + threadIdx.x;
    if (i < n4) cvt_body(X, Hc, Lc, i);
}

__global__ void __launch_bounds__(256) cvt4_k(int n4)
{
    const int a = blockIdx.y;
    int i = blockIdx.x * 256 + threadIdx.x;
    if (i < n4) cvt_body(g_cvt_src[a], g_cvt_dh[a], g_cvt_dl[a], i);
}

__global__ void __launch_bounds__(256) maskf_k(const int* __restrict__ m,
                                              float* __restrict__ mfo, int n)
{
    int i = blockIdx.x * 256 + threadIdx.x;
    if (i < n) mfo[i] = (m[i] != 0) ? 1.f : 0.f;
}

// ------------------------------ launch --------------------------------------
extern "C" void kernel_launch(void* const* d_in, const int* in_sizes, int n_in,
                              void* d_out, int out_size)
{
    const float* x    = (const float*)d_in[0];
    const int*   amsk = (const int*)  d_in[1];
    const float* Wq   = (const float*)d_in[2];
    const float* bq   = (const float*)d_in[3];
    const float* Wk   = (const float*)d_in[4];
    const float* bk   = (const float*)d_in[5];
    const float* Wv   = (const float*)d_in[6];
    const float* bv   = (const float*)d_in[7];
    const float* Wo   = (const float*)d_in[8];
    const float* bo   = (const float*)d_in[9];
    const float* ln1g = (const float*)d_in[10];
    const float* ln1b = (const float*)d_in[11];
    const float* W1   = (const float*)d_in[12];
    const float* b1   = (const float*)d_in[13];
    const float* W2   = (const float*)d_in[14];
    const float* b2   = (const float*)d_in[15];
    const float* ln2g = (const float*)d_in[16];
    const float* ln2b = (const float*)d_in[17];
    float* out = (float*)d_out;

    float *sap, *hp, *f2p, *mfp;
    bf16 *xh, *xl, *qhp, *qlp, *khp, *klp, *vhp, *vlp, *cxh, *cxl;
    bf16 *hhp, *hlp, *fhp, *flp;
    bf16 *wqh, *wql, *wkh, *wkl, *wvh, *wvl, *woh, *wol, *w1h, *w1l, *w2h, *w2l;
    cudaGetSymbolAddress((void**)&sap, g_sa);  cudaGetSymbolAddress((void**)&hp,  g_h);
    cudaGetSymbolAddress((void**)&f2p, g_f2);  cudaGetSymbolAddress((void**)&mfp, g_mf);
    cudaGetSymbolAddress((void**)&xh,  g_xh);  cudaGetSymbolAddress((void**)&xl,  g_xl);
    cudaGetSymbolAddress((void**)&qhp, g_qh);  cudaGetSymbolAddress((void**)&qlp, g_ql);
    cudaGetSymbolAddress((void**)&khp, g_kh);  cudaGetSymbolAddress((void**)&klp, g_kl);
    cudaGetSymbolAddress((void**)&vhp, g_vh);  cudaGetSymbolAddress((void**)&vlp, g_vl);
    cudaGetSymbolAddress((void**)&cxh, g_cxh); cudaGetSymbolAddress((void**)&cxl, g_cxl);
    cudaGetSymbolAddress((void**)&hhp, g_hh);  cudaGetSymbolAddress((void**)&hlp, g_hl);
    cudaGetSymbolAddress((void**)&fhp, g_fh);  cudaGetSymbolAddress((void**)&flp, g_fl);
    cudaGetSymbolAddress((void**)&wqh, g_wqh); cudaGetSymbolAddress((void**)&wql, g_wql);
    cudaGetSymbolAddress((void**)&wkh, g_wkh); cudaGetSymbolAddress((void**)&wkl, g_wkl);
    cudaGetSymbolAddress((void**)&wvh, g_wvh); cudaGetSymbolAddress((void**)&wvl, g_wvl);
    cudaGetSymbolAddress((void**)&woh, g_woh); cudaGetSymbolAddress((void**)&wol, g_wol);
    cudaGetSymbolAddress((void**)&w1h, g_w1h); cudaGetSymbolAddress((void**)&w1l, g_w1l);
    cudaGetSymbolAddress((void**)&w2h, g_w2h); cudaGetSymbolAddress((void**)&w2l, g_w2l);

    static const float* h_src[4];
    static bf16 *h_dh[4], *h_dl[4];
    h_src[0] = Wq; h_src[1] = Wk; h_src[2] = Wv; h_src[3] = Wo;
    h_dh[0] = wqh; h_dh[1] = wkh; h_dh[2] = wvh; h_dh[3] = woh;
    h_dl[0] = wql; h_dl[1] = wkl; h_dl[2] = wvl; h_dl[3] = wol;
    void *d_src_tab, *d_dh_tab, *d_dl_tab;
    cudaGetSymbolAddress(&d_src_tab, g_cvt_src);
    cudaGetSymbolAddress(&d_dh_tab,  g_cvt_dh);
    cudaGetSymbolAddress(&d_dl_tab,  g_cvt_dl);
    cudaMemcpyAsync(d_src_tab, h_src, sizeof(h_src), cudaMemcpyHostToDevice);
    cudaMemcpyAsync(d_dh_tab,  h_dh,  sizeof(h_dh),  cudaMemcpyHostToDevice);
    cudaMemcpyAsync(d_dl_tab,  h_dl,  sizeof(h_dl),  cudaMemcpyHostToDevice);

    cudaFuncSetAttribute(gemm_qkv,            cudaFuncAttributeMaxDynamicSharedMemorySize, GEMM_SMEM);
    cudaFuncSetAttribute(gemm_mma<EPI_RES>,   cudaFuncAttributeMaxDynamicSharedMemorySize, GEMM_SMEM);
    cudaFuncSetAttribute(gemm_mma<EPI_GELU>,  cudaFuncAttributeMaxDynamicSharedMemorySize, GEMM_SMEM);
    cudaFuncSetAttribute(attn_mma, cudaFuncAttributeMaxDynamicSharedMemorySize, ATT_SMEM);

    dim3 gD(Dd/256, TT/128);    // (4, 64)
    dim3 gF(Ff/256, TT/128);    // (16, 64)

    // Launches: 1 cvt_x, 2 cvt4(QKVO weights), 3 maskf, 4 qkv-gemm, 5 attn,
    // 6 O-gemm -> launches 4/5/6 are all tensor kernels.
    cvt_k<<<(TT*Dd/4 + 255)/256, 256>>>(x, xh, xl, TT*Dd/4);                    // 1
    cvt4_k<<<dim3((Dd*Dd/4 + 255)/256, 4), 256>>>(Dd*Dd/4);                     // 2
    maskf_k<<<(Bb*Ss + 255)/256, 256>>>(amsk, mfp, Bb*Ss);                      // 3

    // 4. fused QKV projection
    gemm_qkv<<<dim3(12, TT/128), 256, GEMM_SMEM>>>(xh, xl,
        wqh, wql, wkh, wkl, wvh, wvl, bq, bk, bv,
        qhp, qlp, khp, klp, vhp, vlp);

    // 5. attention -> ctx bf16 hi/lo
    attn_mma<<<dim3(Ss/128, Hh, Bb), 256, ATT_SMEM>>>(qhp, qlp, khp, klp, vhp, vlp,
                                                      mfp, cxh, cxl);

    // 6. output projection + residual (fp32)
    gemm_mma<EPI_RES><<<gD, 256, GEMM_SMEM>>>(cxh, cxl, woh, wol, bo, x,
                                              sap, nullptr, nullptr, Dd, Dd);

    // 7. LN1 -> fp32 + bf16 hi/lo
    ln_k<true><<<TT, 256>>>(sap, ln1g, ln1b, hp, hhp, hlp);

    // 8. cvt W1 (just before first use)
    cvt_k<<<(Ff*Dd/4 + 255)/256, 256>>>(W1, w1h, w1l, Ff*Dd/4);

    // 9. FFN up + gelu -> bf16 hi/lo
    gemm_mma<EPI_GELU><<<gF, 256, GEMM_SMEM>>>(hhp, hlp, w1h, w1l, b1, nullptr,
                                               nullptr, fhp, flp, Ff, Dd);

    // 10. cvt W2
    cvt_k<<<(Dd*Ff/4 + 255)/256, 256>>>(W2, w2h, w2l, Dd*Ff/4);

    // 11. FFN down + residual (fp32)
    gemm_mma<EPI_RES><<<gD, 256, GEMM_SMEM>>>(fhp, flp, w2h, w2l, b2, hp,
                                              f2p, nullptr, nullptr, Dd, Ff);

    // 12. LN2 -> output
    ln_k<false><<<TT, 256>>>(f2p, ln2g, ln2b, out, nullptr, nullptr);
}

// round 10
// speedup vs baseline: 1.3845x; 1.3845x over previous
#include <cuda_runtime.h>
#include <cuda_fp16.h>
#include <math.h>
#include <stdint.h>

// ---------------------------------------------------------------------------
// TransformerBlock B=8 S=1024 D=1024 H=16 DH=64 F=4096 (fp32 in/out)
// All matmuls on mma.sync.m16n8k16 fp16 (2-term hi/lo: (Ah+Al)*Wh), fp32 acc.
// GEMM: BM=128 BN=256 BK=64, 2-stage cp.async pipeline, one sync per k-tile.
// ---------------------------------------------------------------------------

#define Bb 8
#define Ss 1024
#define Dd 1024
#define Hh 16
#define DH 64
#define Ff 4096
#define TT (Bb*Ss)

typedef __half fp16;

// ------------------------- static device scratch ---------------------------
__device__ float g_sa[TT*Dd];
__device__ float g_h [TT*Dd];
__device__ float g_f2[TT*Dd];
__device__ float g_mf[Bb*Ss];

__device__ fp16 g_xh [TT*Dd],  g_xl [TT*Dd];
__device__ fp16 g_qh [TT*Dd],  g_ql [TT*Dd];
__device__ fp16 g_kh [TT*Dd];
__device__ fp16 g_vh [TT*Dd];
__device__ fp16 g_cxh[TT*Dd],  g_cxl[TT*Dd];
__device__ fp16 g_hh [TT*Dd],  g_hl [TT*Dd];
__device__ fp16 g_fh [TT*Ff],  g_fl [TT*Ff];
__device__ fp16 g_wqh[Dd*Dd];
__device__ fp16 g_wkh[Dd*Dd];
__device__ fp16 g_wvh[Dd*Dd];
__device__ fp16 g_woh[Dd*Dd];
__device__ fp16 g_w1h[Ff*Dd];
__device__ fp16 g_w2h[Dd*Ff];

// pointer table for batched weight conversion (hi only)
__device__ const float* g_cvt_src[4];
__device__ fp16*        g_cvt_dh [4];

// ------------------------------ helpers ------------------------------------
__device__ __forceinline__ uint32_t smem_u32(const void* p) {
    uint32_t a;
    asm("{ .reg .u64 t; cvta.to.shared.u64 t, %1; cvt.u32.u64 %0, t; }"
        : "=r"(a) : "l"(p));
    return a;
}
__device__ __forceinline__ void cp16(uint32_t s, const void* g) {
    asm volatile("cp.async.cg.shared.global [%0], [%1], 16;" :: "r"(s), "l"(g));
}
#define CP_COMMIT() asm volatile("cp.async.commit_group;" ::: "memory")
#define CP_WAIT0()  asm volatile("cp.async.wait_group 0;" ::: "memory")

#define SWZ(x)   ((x) ^ (((x) >> 3) & 0x70))   // 128B rows

__device__ __forceinline__ void ldsm4(uint32_t* r, uint32_t a) {
    asm volatile("ldmatrix.sync.aligned.m8n8.x4.shared.b16 {%0,%1,%2,%3}, [%4];"
        : "=r"(r[0]), "=r"(r[1]), "=r"(r[2]), "=r"(r[3]) : "r"(a));
}
__device__ __forceinline__ void ldsm4t(uint32_t* r, uint32_t a) {
    asm volatile("ldmatrix.sync.aligned.m8n8.x4.trans.shared.b16 {%0,%1,%2,%3}, [%4];"
        : "=r"(r[0]), "=r"(r[1]), "=r"(r[2]), "=r"(r[3]) : "r"(a));
}
__device__ __forceinline__ void mma_f16(float* d, const uint32_t* a, const uint32_t* b) {
    asm volatile(
        "mma.sync.aligned.m16n8k16.row.col.f32.f16.f16.f32 "
        "{%0,%1,%2,%3}, {%4,%5,%6,%7}, {%8,%9}, {%0,%1,%2,%3};"
        : "+f"(d[0]), "+f"(d[1]), "+f"(d[2]), "+f"(d[3])
        : "r"(a[0]), "r"(a[1]), "r"(a[2]), "r"(a[3]), "r"(b[0]), "r"(b[1]));
}
__device__ __forceinline__ uint32_t packh(float a, float b) {
    __half2 t = __floats2half2_rn(a, b);
    return reinterpret_cast<uint32_t&>(t);
}
__device__ __forceinline__ float hi16(float v) {
    return __half2float(__float2half(v));
}
__device__ __forceinline__ float gelu_exact(float v) {
    return 0.5f * v * (1.0f + erff(v * 0.70710678118654752440f));
}

// ----------------------------- GEMM core -----------------------------------
// stage: Ah 16K | Al 16K | Wh 32K  = 64K; two stages = 128K smem.
#define GSTG 65536
#define GEMM_SMEM (2*GSTG)

#define EPI_RES   1
#define EPI_GELU  2

// C = (Ah + Al) * Wh^T  (dropped A*Wl term ~2^-11 relative)
template<typename ACC>
__device__ __forceinline__ void gemm_mainloop(
    uint32_t sb, int tid, int lane, int wr, int wc,
    const fp16* A_h, const fp16* A_l, const fp16* W_h,
    int m0, int n0, int K, ACC& acc)
{
    auto load_stage = [&](int st, int kt) {
        const uint32_t s0 = sb + st * GSTG;
        const int k0 = kt * 64;
#pragma unroll
        for (int t = 0; t < 4; t++) {         // A: 128 rows x 128B (hi+lo)
            int idx = t * 256 + tid;
            int row = idx >> 3, c = idx & 7;
            uint32_t off = SWZ((uint32_t)(row * 128 + c * 16));
            size_t go = (size_t)(m0 + row) * K + k0 + c * 8;
            cp16(s0 + off,         A_h + go);
            cp16(s0 + 16384 + off, A_l + go);
        }
#pragma unroll
        for (int t = 0; t < 8; t++) {         // W hi: 256 rows x 128B
            int idx = t * 256 + tid;
            int row = idx >> 3, c = idx & 7;
            uint32_t off = SWZ((uint32_t)(row * 128 + c * 16));
            size_t go = (size_t)(n0 + row) * K + k0 + c * 8;
            cp16(s0 + 32768 + off, W_h + go);
        }
    };

    const int KT = K >> 6;
    load_stage(0, 0);
    CP_COMMIT();

    const int lr16 = lane & 15;
    const int alc  = (lane >> 4) * 16;
    const int brow = wc * 64 + (lane & 7) + ((lane >> 4) & 1) * 8;
    const int bcol = ((lane >> 3) & 1) * 16;

    for (int kt = 0; kt < KT; kt++) {
        CP_WAIT0();
        __syncthreads();
        if (kt + 1 < KT) { load_stage((kt + 1) & 1, kt + 1); CP_COMMIT(); }

        const uint32_t sA  = sb + (kt & 1) * GSTG;
        const uint32_t sAl = sA + 16384;
        const uint32_t sB  = sA + 32768;

#pragma unroll
        for (int ks = 0; ks < 4; ks++) {
            uint32_t ah[4][4], al[4][4];
#pragma unroll
            for (int i = 0; i < 4; i++) {
                uint32_t off = SWZ((uint32_t)((wr * 64 + i * 16 + lr16) * 128 + ks * 32 + alc));
                ldsm4(ah[i], sA  + off);
                ldsm4(al[i], sAl + off);
            }
#pragma unroll
            for (int p = 0; p < 4; p++) {
                uint32_t boff = SWZ((uint32_t)((brow + p * 16) * 128 + ks * 32 + bcol));
                uint32_t bh[4];
                ldsm4(bh, sB + boff);
#pragma unroll
                for (int a = 0; a < 2; a++) {
#pragma unroll
                    for (int i = 0; i < 4; i++) {
                        mma_f16(acc[i][p * 2 + a], ah[i], &bh[2 * a]);
                        mma_f16(acc[i][p * 2 + a], al[i], &bh[2 * a]);
                    }
                }
            }
        }
    }
}

// fused QKV projection: grid (12, 64); blockIdx.x>>2 selects Q/K/V.
// Q writes hi+lo (A-operand of QK); K and V write hi only (B-operands).
__global__ void __launch_bounds__(256) gemm_qkv(
    const fp16* __restrict__ xh, const fp16* __restrict__ xl,
    const fp16* __restrict__ wqh, const fp16* __restrict__ wkh,
    const fp16* __restrict__ wvh,
    const float* __restrict__ bq, const float* __restrict__ bk,
    const float* __restrict__ bv,
    fp16* __restrict__ qh, fp16* __restrict__ ql,
    fp16* __restrict__ kh, fp16* __restrict__ vh)
{
    extern __shared__ char smem[];
    const uint32_t sb = smem_u32(smem);
    const int tid = threadIdx.x;
    const int lane = tid & 31, wid = tid >> 5;
    const int wr = wid >> 2, wc = wid & 3;
    const int mat = blockIdx.x >> 2;
    const int n0 = (blockIdx.x & 3) * 256;
    const int m0 = blockIdx.y * 128;

    const fp16* W_h = (mat == 0) ? wqh : (mat == 1) ? wkh : wvh;
    const float* bias = (mat == 0) ? bq : (mat == 1) ? bk : bv;
    fp16* Ch = (mat == 0) ? qh : (mat == 1) ? kh : vh;
    const float scale = (mat == 0) ? 0.125f : 1.0f;

    float acc[4][8][4];
#pragma unroll
    for (int i = 0; i < 4; i++)
#pragma unroll
        for (int j = 0; j < 8; j++)
#pragma unroll
            for (int e = 0; e < 4; e++) acc[i][j][e] = 0.f;

    gemm_mainloop(sb, tid, lane, wr, wc, xh, xl, W_h, m0, n0, Dd, acc);

#pragma unroll
    for (int i = 0; i < 4; i++) {
        const int r0 = m0 + wr * 64 + i * 16 + (lane >> 2);
#pragma unroll
        for (int j = 0; j < 8; j++) {
            const int n = n0 + wc * 64 + j * 8 + 2 * (lane & 3);
            const float2 b2 = *(const float2*)&bias[n];
#pragma unroll
            for (int hf = 0; hf < 2; hf++) {
                const int m = r0 + hf * 8;
                float v0 = (acc[i][j][hf * 2 + 0] + b2.x) * scale;
                float v1 = (acc[i][j][hf * 2 + 1] + b2.y) * scale;
                const size_t o = (((size_t)(m >> 10) * Hh + (n >> 6)) * Ss + (m & 1023)) * DH + (n & 63);
                const float h0 = hi16(v0);
                const float h1 = hi16(v1);
                *(uint32_t*)(Ch + o) = packh(h0, h1);
                if (mat == 0)
                    *(uint32_t*)(ql + o) = packh(v0 - h0, v1 - h1);
            }
        }
    }
}

template<int EPI>
__global__ void __launch_bounds__(256) gemm_mma(
    const fp16* __restrict__ A_h, const fp16* __restrict__ A_l,
    const fp16* __restrict__ W_h,
    const float* __restrict__ bias, const float* __restrict__ res,
    float* __restrict__ Cf, fp16* __restrict__ Ch, fp16* __restrict__ Cl,
    int N, int K)
{
    extern __shared__ char smem[];
    const uint32_t sb = smem_u32(smem);
    const int tid = threadIdx.x;
    const int lane = tid & 31, wid = tid >> 5;
    const int wr = wid >> 2, wc = wid & 3;
    const int m0 = blockIdx.y * 128, n0 = blockIdx.x * 256;

    float acc[4][8][4];
#pragma unroll
    for (int i = 0; i < 4; i++)
#pragma unroll
        for (int j = 0; j < 8; j++)
#pragma unroll
            for (int e = 0; e < 4; e++) acc[i][j][e] = 0.f;

    gemm_mainloop(sb, tid, lane, wr, wc, A_h, A_l, W_h, m0, n0, K, acc);

#pragma unroll
    for (int i = 0; i < 4; i++) {
        const int r0 = m0 + wr * 64 + i * 16 + (lane >> 2);
#pragma unroll
        for (int j = 0; j < 8; j++) {
            const int n = n0 + wc * 64 + j * 8 + 2 * (lane & 3);
            const float2 b2 = *(const float2*)&bias[n];
#pragma unroll
            for (int hf = 0; hf < 2; hf++) {
                const int m = r0 + hf * 8;
                float v0 = acc[i][j][hf * 2 + 0] + b2.x;
                float v1 = acc[i][j][hf * 2 + 1] + b2.y;
                if (EPI == EPI_RES) {
                    const size_t o = (size_t)m * N + n;
                    const float2 rr = *(const float2*)&res[o];
                    float2 w; w.x = v0 + rr.x; w.y = v1 + rr.y;
                    *(float2*)&Cf[o] = w;
                } else { // EPI_GELU -> fp16 hi/lo
                    const size_t o = (size_t)m * N + n;
                    const float g0 = gelu_exact(v0), g1 = gelu_exact(v1);
                    const float h0 = hi16(g0), h1 = hi16(g1);
                    *(uint32_t*)(Ch + o) = packh(h0, h1);
                    *(uint32_t*)(Cl + o) = packh(g0 - h0, g1 - h1);
                }
            }
        }
    }
}

// --------------------------- flash attention (mma) --------------------------
// Qh 16K | Ql 16K | stage{Kh 16K, Vh 16K} x2 | mask 2x512B
#define ATT_Q   0
#define ATT_ST  32768
#define ATT_STG 32768
#define ATT_MSK (ATT_ST + 2*ATT_STG)
#define ATT_SMEM (ATT_MSK + 1024)

__global__ void __launch_bounds__(256) attn_mma(
    const fp16* __restrict__ qh, const fp16* __restrict__ ql,
    const fp16* __restrict__ kh, const fp16* __restrict__ vh,
    const float* __restrict__ mf,
    fp16* __restrict__ oh, fp16* __restrict__ ol)
{
    extern __shared__ char smem[];
    const uint32_t sb = smem_u32(smem);
    const int tid = threadIdx.x;
    const int lane = tid & 31, wid = tid >> 5;
    const int b = blockIdx.z, h = blockIdx.y, q0 = blockIdx.x * 128;

    const size_t bh_off = ((size_t)(b * Hh + h) * Ss) * DH;
    const fp16* qhp = qh + bh_off + (size_t)q0 * DH;
    const fp16* qlp = ql + bh_off + (size_t)q0 * DH;
    const fp16* khp = kh + bh_off;
    const fp16* vhp = vh + bh_off;
    const float* mfb = mf + b * Ss;

    auto load_kv = [&](int st, int kt) {
        const uint32_t s0 = sb + ATT_ST + st * ATT_STG;
        const int kv0 = kt * 128;
#pragma unroll
        for (int t = 0; t < 4; t++) {
            int idx = t * 256 + tid;
            int row = idx >> 3, c = idx & 7;
            uint32_t off = SWZ((uint32_t)(row * 128 + c * 16));
            size_t go = (size_t)(kv0 + row) * DH + c * 8;
            cp16(s0 + off,         khp + go);
            cp16(s0 + 16384 + off, vhp + go);
        }
        if (tid < 32) cp16(sb + ATT_MSK + st * 512 + tid * 16, mfb + kv0 + tid * 4);
    };

    {
#pragma unroll
        for (int t = 0; t < 4; t++) {
            int idx = t * 256 + tid;
            int row = idx >> 3, c = idx & 7;
            uint32_t off = SWZ((uint32_t)(row * 128 + c * 16));
            size_t go = (size_t)row * DH + c * 8;
            cp16(sb + ATT_Q + off,         qhp + go);
            cp16(sb + ATT_Q + 16384 + off, qlp + go);
        }
        load_kv(0, 0);
        CP_COMMIT();
    }

    uint32_t qfh[4][4], qfl[4][4];
    float oacc[8][4];
#pragma unroll
    for (int q = 0; q < 8; q++)
#pragma unroll
        for (int e = 0; e < 4; e++) oacc[q][e] = 0.f;
    float mrow0 = -INFINITY, mrow1 = -INFINITY, lsum0 = 0.f, lsum1 = 0.f;

    const int lr16 = lane & 15;
    const int alc  = (lane >> 4) * 16;
    const int brow = (lane & 7) + ((lane >> 4) & 1) * 8;
    const int bcol = ((lane >> 3) & 1) * 16;
    const int vrow = (lane & 7) + ((lane >> 3) & 1) * 8;
    const int vcol = (lane >> 4) * 16;

    const int NKV = Ss / 128;
    for (int kt = 0; kt < NKV; kt++) {
        CP_WAIT0();
        __syncthreads();
        if (kt + 1 < NKV) { load_kv((kt + 1) & 1, kt + 1); CP_COMMIT(); }

        if (kt == 0) {
#pragma unroll
            for (int ks = 0; ks < 4; ks++) {
                uint32_t off = SWZ((uint32_t)((wid * 16 + lr16) * 128 + ks * 32 + alc));
                ldsm4(qfh[ks], sb + ATT_Q + off);
                ldsm4(qfl[ks], sb + ATT_Q + 16384 + off);
            }
        }

        const uint32_t sK = sb + ATT_ST + (kt & 1) * ATT_STG;
        const uint32_t sV = sK + 16384;
        const uint32_t sM = sb + ATT_MSK + (kt & 1) * 512;

        float sacc[16][4];
#pragma unroll
        for (int j = 0; j < 16; j++)
#pragma unroll
            for (int e = 0; e < 4; e++) sacc[j][e] = 0.f;

#pragma unroll
        for (int p = 0; p < 8; p++) {
#pragma unroll
            for (int ks = 0; ks < 4; ks++) {
                uint32_t koff = SWZ((uint32_t)((p * 16 + brow) * 128 + ks * 32 + bcol));
                uint32_t kbh[4];
                ldsm4(kbh, sK + koff);
#pragma unroll
                for (int a = 0; a < 2; a++) {
                    mma_f16(sacc[p * 2 + a], qfh[ks], &kbh[2 * a]);
                    mma_f16(sacc[p * 2 + a], qfl[ks], &kbh[2 * a]);
                }
            }
        }

        float mx0 = -INFINITY, mx1 = -INFINITY;
#pragma unroll
        for (int j = 0; j < 16; j++) {
            mx0 = fmaxf(mx0, fmaxf(sacc[j][0], sacc[j][1]));
            mx1 = fmaxf(mx1, fmaxf(sacc[j][2], sacc[j][3]));
        }
        mx0 = fmaxf(mx0, __shfl_xor_sync(0xffffffffu, mx0, 1));
        mx0 = fmaxf(mx0, __shfl_xor_sync(0xffffffffu, mx0, 2));
        mx1 = fmaxf(mx1, __shfl_xor_sync(0xffffffffu, mx1, 1));
        mx1 = fmaxf(mx1, __shfl_xor_sync(0xffffffffu, mx1, 2));
        const float mnew0 = fmaxf(mrow0, mx0);
        const float mnew1 = fmaxf(mrow1, mx1);
        const float al0 = __expf(mrow0 - mnew0);
        const float al1 = __expf(mrow1 - mnew1);
        float ls0 = 0.f, ls1 = 0.f;
#pragma unroll
        for (int j = 0; j < 16; j++) {
            float2 mv;
            asm volatile("ld.shared.v2.f32 {%0,%1}, [%2];"
                : "=f"(mv.x), "=f"(mv.y)
                : "r"(sM + (uint32_t)((j * 8 + 2 * (lane & 3)) * 4)));
            float p0 = __expf(sacc[j][0] - mnew0) * mv.x;
            float p1 = __expf(sacc[j][1] - mnew0) * mv.y;
            float p2 = __expf(sacc[j][2] - mnew1) * mv.x;
            float p3 = __expf(sacc[j][3] - mnew1) * mv.y;
            sacc[j][0] = p0; sacc[j][1] = p1; sacc[j][2] = p2; sacc[j][3] = p3;
            ls0 += p0 + p1; ls1 += p2 + p3;
        }
        ls0 += __shfl_xor_sync(0xffffffffu, ls0, 1);
        ls0 += __shfl_xor_sync(0xffffffffu, ls0, 2);
        ls1 += __shfl_xor_sync(0xffffffffu, ls1, 1);
        ls1 += __shfl_xor_sync(0xffffffffu, ls1, 2);
        lsum0 = lsum0 * al0 + ls0;
        lsum1 = lsum1 * al1 + ls1;
        mrow0 = mnew0; mrow1 = mnew1;
#pragma unroll
        for (int q = 0; q < 8; q++) {
            oacc[q][0] *= al0; oacc[q][1] *= al0;
            oacc[q][2] *= al1; oacc[q][3] *= al1;
        }

        // O += P * Vh  (P as fp16 hi+lo -> exact to 2^-22; V truncated ~2^-11)
#pragma unroll
        for (int ks = 0; ks < 8; ks++) {
            uint32_t ph[4], pl[4];
            {
                const float* s0 = sacc[2 * ks];
                const float* s1 = sacc[2 * ks + 1];
                float h00 = hi16(s0[0]), h01 = hi16(s0[1]);
                float h02 = hi16(s0[2]), h03 = hi16(s0[3]);
                float h10 = hi16(s1[0]), h11 = hi16(s1[1]);
                float h12 = hi16(s1[2]), h13 = hi16(s1[3]);
                ph[0] = packh(h00, h01); ph[1] = packh(h02, h03);
                ph[2] = packh(h10, h11); ph[3] = packh(h12, h13);
                pl[0] = packh(s0[0] - h00, s0[1] - h01);
                pl[1] = packh(s0[2] - h02, s0[3] - h03);
                pl[2] = packh(s1[0] - h10, s1[1] - h11);
                pl[3] = packh(s1[2] - h12, s1[3] - h13);
            }
#pragma unroll
            for (int q = 0; q < 4; q++) {
                uint32_t voff = SWZ((uint32_t)((ks * 16 + vrow) * 128 + q * 32 + vcol));
                uint32_t vbh[4];
                ldsm4t(vbh, sV + voff);
#pragma unroll
                for (int a = 0; a < 2; a++) {
                    mma_f16(oacc[q * 2 + a], ph, &vbh[2 * a]);
                    mma_f16(oacc[q * 2 + a], pl, &vbh[2 * a]);
                }
            }
        }
    }

    const float inv0 = 1.f / lsum0;
    const float inv1 = 1.f / lsum1;
    const int tok0 = b * Ss + q0 + wid * 16 + (lane >> 2);
#pragma unroll
    for (int q = 0; q < 8; q++) {
        const int col = h * DH + q * 8 + 2 * (lane & 3);
        {
            float v0 = oacc[q][0] * inv0, v1 = oacc[q][1] * inv0;
            const size_t o = (size_t)tok0 * Dd + col;
            float h0 = hi16(v0), h1 = hi16(v1);
            *(uint32_t*)(oh + o) = packh(h0, h1);
            *(uint32_t*)(ol + o) = packh(v0 - h0, v1 - h1);
        }
        {
            float v0 = oacc[q][2] * inv1, v1 = oacc[q][3] * inv1;
            const size_t o = (size_t)(tok0 + 8) * Dd + col;
            float h0 = hi16(v0), h1 = hi16(v1);
            *(uint32_t*)(oh + o) = packh(h0, h1);
            *(uint32_t*)(ol + o) = packh(v0 - h0, v1 - h1);
        }
    }
}

// ------------------------------ LayerNorm -----------------------------------
template<bool WB>
__global__ void __launch_bounds__(256) ln_k(
    const float* __restrict__ X, const float* __restrict__ gg,
    const float* __restrict__ bb, float* __restrict__ Y,
    fp16* __restrict__ Yh, fp16* __restrict__ Yl)
{
    __shared__ float red[16];
    const int row = blockIdx.x, tid = threadIdx.x;
    const float4 x = ((const float4*)(X + (size_t)row * Dd))[tid];
    float s  = x.x + x.y + x.z + x.w;
    float s2 = x.x*x.x + x.y*x.y + x.z*x.z + x.w*x.w;
#pragma unroll
    for (int o = 16; o; o >>= 1) {
        s  += __shfl_xor_sync(0xffffffffu, s,  o);
        s2 += __shfl_xor_sync(0xffffffffu, s2, o);
    }
    const int w = tid >> 5, lane = tid & 31;
    if (lane == 0) { red[w] = s; red[8 + w] = s2; }
    __syncthreads();
    if (tid < 32) {
        float a = (tid < 8) ? red[tid]     : 0.f;
        float c = (tid < 8) ? red[8 + tid] : 0.f;
#pragma unroll
        for (int o = 4; o; o >>= 1) {
            a += __shfl_xor_sync(0xffffffffu, a, o);
            c += __shfl_xor_sync(0xffffffffu, c, o);
        }
        if (tid == 0) { red[0] = a; red[8] = c; }
    }
    __syncthreads();
    const float mean = red[0] * (1.f / Dd);
    const float var  = red[8] * (1.f / Dd) - mean * mean;
    const float rstd = rsqrtf(var + 1e-12f);
    const float4 gv = ((const float4*)gg)[tid];
    const float4 bv = ((const float4*)bb)[tid];
    float4 y;
    y.x = (x.x - mean) * rstd * gv.x + bv.x;
    y.y = (x.y - mean) * rstd * gv.y + bv.y;
    y.z = (x.z - mean) * rstd * gv.z + bv.z;
    y.w = (x.w - mean) * rstd * gv.w + bv.w;
    ((float4*)(Y + (size_t)row * Dd))[tid] = y;
    if (WB) {
        float h0 = hi16(y.x), h1 = hi16(y.y), h2 = hi16(y.z), h3 = hi16(y.w);
        uint2 vh2, vl2;
        vh2.x = packh(h0, h1);              vh2.y = packh(h2, h3);
        vl2.x = packh(y.x - h0, y.y - h1);  vl2.y = packh(y.z - h2, y.w - h3);
        ((uint2*)(Yh + (size_t)row * Dd))[tid] = vh2;
        ((uint2*)(Yl + (size_t)row * Dd))[tid] = vl2;
    }
}

// -------------------------- fp32 -> fp16 conversions ------------------------
__device__ __forceinline__ void cvt_body(const float* __restrict__ X,
                                         fp16* __restrict__ Hc,
                                         fp16* __restrict__ Lc, int i)
{
    float4 v = ((const float4*)X)[i];
    float h0 = hi16(v.x), h1 = hi16(v.y), h2 = hi16(v.z), h3 = hi16(v.w);
    uint2 vh2, vl2;
    vh2.x = packh(h0, h1);              vh2.y = packh(h2, h3);
    vl2.x = packh(v.x - h0, v.y - h1);  vl2.y = packh(v.z - h2, v.w - h3);
    ((uint2*)Hc)[i] = vh2;
    ((uint2*)Lc)[i] = vl2;
}

__global__ void __launch_bounds__(256) cvt_k(
    const float* __restrict__ X, fp16* __restrict__ Hc,
    fp16* __restrict__ Lc, int n4)
{
    int i = blockIdx.x * 256 + threadIdx.x;
    if (i < n4) cvt_body(X, Hc, Lc, i);
}

// hi-only conversion (weights)
__global__ void __launch_bounds__(256) cvth_k(
    const float* __restrict__ X, fp16* __restrict__ Hc, int n4)
{
    int i = blockIdx.x * 256 + threadIdx.x;
    if (i >= n4) return;
    float4 v = ((const float4*)X)[i];
    uint2 vh2;
    vh2.x = packh(v.x, v.y);  vh2.y = packh(v.z, v.w);
    ((uint2*)Hc)[i] = vh2;
}

__global__ void __launch_bounds__(256) cvt4h_k(int n4)
{
    const int a = blockIdx.y;
    int i = blockIdx.x * 256 + threadIdx.x;
    if (i >= n4) return;
    const float* X = g_cvt_src[a];
    fp16* Hc = g_cvt_dh[a];
    float4 v = ((const float4*)X)[i];
    uint2 vh2;
    vh2.x = packh(v.x, v.y);  vh2.y = packh(v.z, v.w);
    ((uint2*)Hc)[i] = vh2;
}

__global__ void __launch_bounds__(256) maskf_k(const int* __restrict__ m,
                                              float* __restrict__ mfo, int n)
{
    int i = blockIdx.x * 256 + threadIdx.x;
    if (i < n) mfo[i] = (m[i] != 0) ? 1.f : 0.f;
}

// ------------------------------ launch --------------------------------------
extern "C" void kernel_launch(void* const* d_in, const int* in_sizes, int n_in,
                              void* d_out, int out_size)
{
    const float* x    = (const float*)d_in[0];
    const int*   amsk = (const int*)  d_in[1];
    const float* Wq   = (const float*)d_in[2];
    const float* bq   = (const float*)d_in[3];
    const float* Wk   = (const float*)d_in[4];
    const float* bk   = (const float*)d_in[5];
    const float* Wv   = (const float*)d_in[6];
    const float* bv   = (const float*)d_in[7];
    const float* Wo   = (const float*)d_in[8];
    const float* bo   = (const float*)d_in[9];
    const float* ln1g = (const float*)d_in[10];
    const float* ln1b = (const float*)d_in[11];
    const float* W1   = (const float*)d_in[12];
    const float* b1   = (const float*)d_in[13];
    const float* W2   = (const float*)d_in[14];
    const float* b2   = (const float*)d_in[15];
    const float* ln2g = (const float*)d_in[16];
    const float* ln2b = (const float*)d_in[17];
    float* out = (float*)d_out;

    float *sap, *hp, *f2p, *mfp;
    fp16 *xh, *xl, *qhp, *qlp, *khp, *vhp, *cxh, *cxl;
    fp16 *hhp, *hlp, *fhp, *flp;
    fp16 *wqh, *wkh, *wvh, *woh, *w1h, *w2h;
    cudaGetSymbolAddress((void**)&sap, g_sa);  cudaGetSymbolAddress((void**)&hp,  g_h);
    cudaGetSymbolAddress((void**)&f2p, g_f2);  cudaGetSymbolAddress((void**)&mfp, g_mf);
    cudaGetSymbolAddress((void**)&xh,  g_xh);  cudaGetSymbolAddress((void**)&xl,  g_xl);
    cudaGetSymbolAddress((void**)&qhp, g_qh);  cudaGetSymbolAddress((void**)&qlp, g_ql);
    cudaGetSymbolAddress((void**)&khp, g_kh);  cudaGetSymbolAddress((void**)&vhp, g_vh);
    cudaGetSymbolAddress((void**)&cxh, g_cxh); cudaGetSymbolAddress((void**)&cxl, g_cxl);
    cudaGetSymbolAddress((void**)&hhp, g_hh);  cudaGetSymbolAddress((void**)&hlp, g_hl);
    cudaGetSymbolAddress((void**)&fhp, g_fh);  cudaGetSymbolAddress((void**)&flp, g_fl);
    cudaGetSymbolAddress((void**)&wqh, g_wqh); cudaGetSymbolAddress((void**)&wkh, g_wkh);
    cudaGetSymbolAddress((void**)&wvh, g_wvh); cudaGetSymbolAddress((void**)&woh, g_woh);
    cudaGetSymbolAddress((void**)&w1h, g_w1h); cudaGetSymbolAddress((void**)&w2h, g_w2h);

    static const float* h_src[4];
    static fp16* h_dh[4];
    h_src[0] = Wq; h_src[1] = Wk; h_src[2] = Wv; h_src[3] = Wo;
    h_dh[0] = wqh; h_dh[1] = wkh; h_dh[2] = wvh; h_dh[3] = woh;
    void *d_src_tab, *d_dh_tab;
    cudaGetSymbolAddress(&d_src_tab, g_cvt_src);
    cudaGetSymbolAddress(&d_dh_tab,  g_cvt_dh);
    cudaMemcpyAsync(d_src_tab, h_src, sizeof(h_src), cudaMemcpyHostToDevice);
    cudaMemcpyAsync(d_dh_tab,  h_dh,  sizeof(h_dh),  cudaMemcpyHostToDevice);

    cudaFuncSetAttribute(gemm_qkv,           cudaFuncAttributeMaxDynamicSharedMemorySize, GEMM_SMEM);
    cudaFuncSetAttribute(gemm_mma<EPI_RES>,  cudaFuncAttributeMaxDynamicSharedMemorySize, GEMM_SMEM);
    cudaFuncSetAttribute(gemm_mma<EPI_GELU>, cudaFuncAttributeMaxDynamicSharedMemorySize, GEMM_SMEM);
    cudaFuncSetAttribute(attn_mma, cudaFuncAttributeMaxDynamicSharedMemorySize, ATT_SMEM);

    dim3 gD(Dd/256, TT/128);    // (4, 64)
    dim3 gF(Ff/256, TT/128);    // (16, 64)

    // Launches: 1 cvt_x, 2 cvt4h(QKVO weights hi), 3 maskf, 4 qkv, 5 attn, 6 O.
    cvt_k<<<(TT*Dd/4 + 255)/256, 256>>>(x, xh, xl, TT*Dd/4);                    // 1
    cvt4h_k<<<dim3((Dd*Dd/4 + 255)/256, 4), 256>>>(Dd*Dd/4);                    // 2
    maskf_k<<<(Bb*Ss + 255)/256, 256>>>(amsk, mfp, Bb*Ss);                      // 3

    // 4. fused QKV projection
    gemm_qkv<<<dim3(12, TT/128), 256, GEMM_SMEM>>>(xh, xl, wqh, wkh, wvh,
                                                   bq, bk, bv,
                                                   qhp, qlp, khp, vhp);

    // 5. attention -> ctx fp16 hi/lo
    attn_mma<<<dim3(Ss/128, Hh, Bb), 256, ATT_SMEM>>>(qhp, qlp, khp, vhp,
                                                      mfp, cxh, cxl);

    // 6. output projection + residual (fp32)
    gemm_mma<EPI_RES><<<gD, 256, GEMM_SMEM>>>(cxh, cxl, woh, bo, x,
                                              sap, nullptr, nullptr, Dd, Dd);

    // 7. LN1 -> fp32 + fp16 hi/lo
    ln_k<true><<<TT, 256>>>(sap, ln1g, ln1b, hp, hhp, hlp);

    // 8. cvt W1 (hi only)
    cvth_k<<<(Ff*Dd/4 + 255)/256, 256>>>(W1, w1h, Ff*Dd/4);

    // 9. FFN up + gelu -> fp16 hi/lo
    gemm_mma<EPI_GELU><<<gF, 256, GEMM_SMEM>>>(hhp, hlp, w1h, b1, nullptr,
                                               nullptr, fhp, flp, Ff, Dd);

    // 10. cvt W2 (hi only)
    cvth_k<<<(Dd*Ff/4 + 255)/256, 256>>>(W2, w2h, Dd*Ff/4);

    // 11. FFN down + residual (fp32)
    gemm_mma<EPI_RES><<<gD, 256, GEMM_SMEM>>>(fhp, flp, w2h, b2, hp,
                                              f2p, nullptr, nullptr, Dd, Ff);

    // 12. LN2 -> output
    ln_k<false><<<TT, 256>>>(f2p, ln2g, ln2b, out, nullptr, nullptr);
}

// round 12
// speedup vs baseline: 1.5325x; 1.1069x over previous
#include <cuda_runtime.h>
#include <cuda_fp16.h>
#include <math.h>
#include <stdint.h>

// ---------------------------------------------------------------------------
// TransformerBlock B=8 S=1024 D=1024 H=16 DH=64 F=4096 (fp32 in/out)
// All matmuls: plain fp16 mma.sync.m16n8k16, fp32 accumulate.
// GEMM: BM=128 BN=256 BK=64, 2-stage cp.async pipeline, one sync per k-tile.
// ---------------------------------------------------------------------------

#define Bb 8
#define Ss 1024
#define Dd 1024
#define Hh 16
#define DH 64
#define Ff 4096
#define TT (Bb*Ss)

typedef __half fp16;

// ------------------------- static device scratch ---------------------------
__device__ float g_sa[TT*Dd];
__device__ float g_h [TT*Dd];
__device__ float g_f2[TT*Dd];
__device__ float g_mf[Bb*Ss];

__device__ fp16 g_xh [TT*Dd];
__device__ fp16 g_qh [TT*Dd];
__device__ fp16 g_kh [TT*Dd];
__device__ fp16 g_vh [TT*Dd];
__device__ fp16 g_cxh[TT*Dd];
__device__ fp16 g_hh [TT*Dd];
__device__ fp16 g_fh [TT*Ff];
__device__ fp16 g_wqh[Dd*Dd];
__device__ fp16 g_wkh[Dd*Dd];
__device__ fp16 g_wvh[Dd*Dd];
__device__ fp16 g_woh[Dd*Dd];
__device__ fp16 g_w1h[Ff*Dd];
__device__ fp16 g_w2h[Dd*Ff];

// pointer table for batched weight conversion (hi only)
__device__ const float* g_cvt_src[4];
__device__ fp16*        g_cvt_dh [4];

// ------------------------------ helpers ------------------------------------
__device__ __forceinline__ uint32_t smem_u32(const void* p) {
    uint32_t a;
    asm("{ .reg .u64 t; cvta.to.shared.u64 t, %1; cvt.u32.u64 %0, t; }"
        : "=r"(a) : "l"(p));
    return a;
}
__device__ __forceinline__ void cp16(uint32_t s, const void* g) {
    asm volatile("cp.async.cg.shared.global [%0], [%1], 16;" :: "r"(s), "l"(g));
}
#define CP_COMMIT() asm volatile("cp.async.commit_group;" ::: "memory")
#define CP_WAIT0()  asm volatile("cp.async.wait_group 0;" ::: "memory")

#define SWZ(x)   ((x) ^ (((x) >> 3) & 0x70))   // 128B rows

__device__ __forceinline__ void ldsm4(uint32_t* r, uint32_t a) {
    asm volatile("ldmatrix.sync.aligned.m8n8.x4.shared.b16 {%0,%1,%2,%3}, [%4];"
        : "=r"(r[0]), "=r"(r[1]), "=r"(r[2]), "=r"(r[3]) : "r"(a));
}
__device__ __forceinline__ void ldsm4t(uint32_t* r, uint32_t a) {
    asm volatile("ldmatrix.sync.aligned.m8n8.x4.trans.shared.b16 {%0,%1,%2,%3}, [%4];"
        : "=r"(r[0]), "=r"(r[1]), "=r"(r[2]), "=r"(r[3]) : "r"(a));
}
__device__ __forceinline__ void mma_f16(float* d, const uint32_t* a, const uint32_t* b) {
    asm volatile(
        "mma.sync.aligned.m16n8k16.row.col.f32.f16.f16.f32 "
        "{%0,%1,%2,%3}, {%4,%5,%6,%7}, {%8,%9}, {%0,%1,%2,%3};"
        : "+f"(d[0]), "+f"(d[1]), "+f"(d[2]), "+f"(d[3])
        : "r"(a[0]), "r"(a[1]), "r"(a[2]), "r"(a[3]), "r"(b[0]), "r"(b[1]));
}
__device__ __forceinline__ uint32_t packh(float a, float b) {
    __half2 t = __floats2half2_rn(a, b);
    return reinterpret_cast<uint32_t&>(t);
}
__device__ __forceinline__ float gelu_exact(float v) {
    return 0.5f * v * (1.0f + erff(v * 0.70710678118654752440f));
}

// ----------------------------- GEMM core -----------------------------------
// stage: A 16K | W 32K = 48K; two stages = 96K smem.
#define GSTG 49152
#define GEMM_SMEM (2*GSTG)

#define EPI_RES   1
#define EPI_GELU  2

template<typename ACC>
__device__ __forceinline__ void gemm_mainloop(
    uint32_t sb, int tid, int lane, int wr, int wc,
    const fp16* A_h, const fp16* W_h,
    int m0, int n0, int K, ACC& acc)
{
    auto load_stage = [&](int st, int kt) {
        const uint32_t s0 = sb + st * GSTG;
        const int k0 = kt * 64;
#pragma unroll
        for (int t = 0; t < 4; t++) {         // A: 128 rows x 128B
            int idx = t * 256 + tid;
            int row = idx >> 3, c = idx & 7;
            uint32_t off = SWZ((uint32_t)(row * 128 + c * 16));
            size_t go = (size_t)(m0 + row) * K + k0 + c * 8;
            cp16(s0 + off, A_h + go);
        }
#pragma unroll
        for (int t = 0; t < 8; t++) {         // W: 256 rows x 128B
            int idx = t * 256 + tid;
            int row = idx >> 3, c = idx & 7;
            uint32_t off = SWZ((uint32_t)(row * 128 + c * 16));
            size_t go = (size_t)(n0 + row) * K + k0 + c * 8;
            cp16(s0 + 16384 + off, W_h + go);
        }
    };

    const int KT = K >> 6;
    load_stage(0, 0);
    CP_COMMIT();

    const int lr16 = lane & 15;
    const int alc  = (lane >> 4) * 16;
    const int brow = wc * 64 + (lane & 7) + ((lane >> 4) & 1) * 8;
    const int bcol = ((lane >> 3) & 1) * 16;

    for (int kt = 0; kt < KT; kt++) {
        CP_WAIT0();
        __syncthreads();
        if (kt + 1 < KT) { load_stage((kt + 1) & 1, kt + 1); CP_COMMIT(); }

        const uint32_t sA = sb + (kt & 1) * GSTG;
        const uint32_t sB = sA + 16384;

#pragma unroll
        for (int ks = 0; ks < 4; ks++) {
            uint32_t ah[4][4];
#pragma unroll
            for (int i = 0; i < 4; i++) {
                uint32_t off = SWZ((uint32_t)((wr * 64 + i * 16 + lr16) * 128 + ks * 32 + alc));
                ldsm4(ah[i], sA + off);
            }
#pragma unroll
            for (int p = 0; p < 4; p++) {
                uint32_t boff = SWZ((uint32_t)((brow + p * 16) * 128 + ks * 32 + bcol));
                uint32_t bh[4];
                ldsm4(bh, sB + boff);
#pragma unroll
                for (int a = 0; a < 2; a++) {
#pragma unroll
                    for (int i = 0; i < 4; i++)
                        mma_f16(acc[i][p * 2 + a], ah[i], &bh[2 * a]);
                }
            }
        }
    }
}

// fused QKV projection: grid (12, 64); blockIdx.x>>2 selects Q/K/V
__global__ void __launch_bounds__(256) gemm_qkv(
    const fp16* __restrict__ xh,
    const fp16* __restrict__ wqh, const fp16* __restrict__ wkh,
    const fp16* __restrict__ wvh,
    const float* __restrict__ bq, const float* __restrict__ bk,
    const float* __restrict__ bv,
    fp16* __restrict__ qh, fp16* __restrict__ kh, fp16* __restrict__ vh)
{
    extern __shared__ char smem[];
    const uint32_t sb = smem_u32(smem);
    const int tid = threadIdx.x;
    const int lane = tid & 31, wid = tid >> 5;
    const int wr = wid >> 2, wc = wid & 3;
    const int mat = blockIdx.x >> 2;
    const int n0 = (blockIdx.x & 3) * 256;
    const int m0 = blockIdx.y * 128;

    const fp16* W_h = (mat == 0) ? wqh : (mat == 1) ? wkh : wvh;
    const float* bias = (mat == 0) ? bq : (mat == 1) ? bk : bv;
    fp16* Ch = (mat == 0) ? qh : (mat == 1) ? kh : vh;
    const float scale = (mat == 0) ? 0.125f : 1.0f;

    float acc[4][8][4];
#pragma unroll
    for (int i = 0; i < 4; i++)
#pragma unroll
        for (int j = 0; j < 8; j++)
#pragma unroll
            for (int e = 0; e < 4; e++) acc[i][j][e] = 0.f;

    gemm_mainloop(sb, tid, lane, wr, wc, xh, W_h, m0, n0, Dd, acc);

#pragma unroll
    for (int i = 0; i < 4; i++) {
        const int r0 = m0 + wr * 64 + i * 16 + (lane >> 2);
#pragma unroll
        for (int j = 0; j < 8; j++) {
            const int n = n0 + wc * 64 + j * 8 + 2 * (lane & 3);
            const float2 b2 = *(const float2*)&bias[n];
#pragma unroll
            for (int hf = 0; hf < 2; hf++) {
                const int m = r0 + hf * 8;
                float v0 = (acc[i][j][hf * 2 + 0] + b2.x) * scale;
                float v1 = (acc[i][j][hf * 2 + 1] + b2.y) * scale;
                const size_t o = (((size_t)(m >> 10) * Hh + (n >> 6)) * Ss + (m & 1023)) * DH + (n & 63);
                *(uint32_t*)(Ch + o) = packh(v0, v1);
            }
        }
    }
}

template<int EPI>
__global__ void __launch_bounds__(256) gemm_mma(
    const fp16* __restrict__ A_h, const fp16* __restrict__ W_h,
    const float* __restrict__ bias, const float* __restrict__ res,
    float* __restrict__ Cf, fp16* __restrict__ Ch,
    int N, int K)
{
    extern __shared__ char smem[];
    const uint32_t sb = smem_u32(smem);
    const int tid = threadIdx.x;
    const int lane = tid & 31, wid = tid >> 5;
    const int wr = wid >> 2, wc = wid & 3;
    const int m0 = blockIdx.y * 128, n0 = blockIdx.x * 256;

    float acc[4][8][4];
#pragma unroll
    for (int i = 0; i < 4; i++)
#pragma unroll
        for (int j = 0; j < 8; j++)
#pragma unroll
            for (int e = 0; e < 4; e++) acc[i][j][e] = 0.f;

    gemm_mainloop(sb, tid, lane, wr, wc, A_h, W_h, m0, n0, K, acc);

#pragma unroll
    for (int i = 0; i < 4; i++) {
        const int r0 = m0 + wr * 64 + i * 16 + (lane >> 2);
#pragma unroll
        for (int j = 0; j < 8; j++) {
            const int n = n0 + wc * 64 + j * 8 + 2 * (lane & 3);
            const float2 b2 = *(const float2*)&bias[n];
#pragma unroll
            for (int hf = 0; hf < 2; hf++) {
                const int m = r0 + hf * 8;
                float v0 = acc[i][j][hf * 2 + 0] + b2.x;
                float v1 = acc[i][j][hf * 2 + 1] + b2.y;
                if (EPI == EPI_RES) {
                    const size_t o = (size_t)m * N + n;
                    const float2 rr = *(const float2*)&res[o];
                    float2 w; w.x = v0 + rr.x; w.y = v1 + rr.y;
                    *(float2*)&Cf[o] = w;
                } else { // EPI_GELU -> fp16
                    const size_t o = (size_t)m * N + n;
                    *(uint32_t*)(Ch + o) = packh(gelu_exact(v0), gelu_exact(v1));
                }
            }
        }
    }
}

// --------------------------- flash attention (mma) --------------------------
// Q 16K | stage{Kh 16K, Vh 16K} x2 | mask 2x512B
#define ATT_Q   0
#define ATT_ST  16384
#define ATT_STG 32768
#define ATT_MSK (ATT_ST + 2*ATT_STG)
#define ATT_SMEM (ATT_MSK + 1024)

__global__ void __launch_bounds__(256) attn_mma(
    const fp16* __restrict__ qh, const fp16* __restrict__ kh,
    const fp16* __restrict__ vh,
    const float* __restrict__ mf,
    fp16* __restrict__ oh)
{
    extern __shared__ char smem[];
    const uint32_t sb = smem_u32(smem);
    const int tid = threadIdx.x;
    const int lane = tid & 31, wid = tid >> 5;
    const int b = blockIdx.z, h = blockIdx.y, q0 = blockIdx.x * 128;

    const size_t bh_off = ((size_t)(b * Hh + h) * Ss) * DH;
    const fp16* qhp = qh + bh_off + (size_t)q0 * DH;
    const fp16* khp = kh + bh_off;
    const fp16* vhp = vh + bh_off;
    const float* mfb = mf + b * Ss;

    auto load_kv = [&](int st, int kt) {
        const uint32_t s0 = sb + ATT_ST + st * ATT_STG;
        const int kv0 = kt * 128;
#pragma unroll
        for (int t = 0; t < 4; t++) {
            int idx = t * 256 + tid;
            int row = idx >> 3, c = idx & 7;
            uint32_t off = SWZ((uint32_t)(row * 128 + c * 16));
            size_t go = (size_t)(kv0 + row) * DH + c * 8;
            cp16(s0 + off,         khp + go);
            cp16(s0 + 16384 + off, vhp + go);
        }
        if (tid < 32) cp16(sb + ATT_MSK + st * 512 + tid * 16, mfb + kv0 + tid * 4);
    };

    {
        // Q prologue: proven indexing (swizzle applied to full offset per 16B chunk)
#pragma unroll
        for (int t = 0; t < 4; t++) {
            int idx = t * 256 + tid;          // 0..1023
            int row = idx >> 3, c = idx & 7;  // 128 rows x 8 chunks of 16B
            uint32_t off = SWZ((uint32_t)(row * 128 + c * 16));
            size_t go = (size_t)row * DH + c * 8;
            cp16(sb + ATT_Q + off, qhp + go);
        }
        load_kv(0, 0);
        CP_COMMIT();
    }

    uint32_t qfh[4][4];
    float oacc[8][4];
#pragma unroll
    for (int q = 0; q < 8; q++)
#pragma unroll
        for (int e = 0; e < 4; e++) oacc[q][e] = 0.f;
    float mrow0 = -INFINITY, mrow1 = -INFINITY, lsum0 = 0.f, lsum1 = 0.f;

    const int lr16 = lane & 15;
    const int alc  = (lane >> 4) * 16;
    const int brow = (lane & 7) + ((lane >> 4) & 1) * 8;
    const int bcol = ((lane >> 3) & 1) * 16;
    const int vrow = (lane & 7) + ((lane >> 3) & 1) * 8;
    const int vcol = (lane >> 4) * 16;

    const int NKV = Ss / 128;
    for (int kt = 0; kt < NKV; kt++) {
        CP_WAIT0();
        __syncthreads();
        if (kt + 1 < NKV) { load_kv((kt + 1) & 1, kt + 1); CP_COMMIT(); }

        if (kt == 0) {
#pragma unroll
            for (int ks = 0; ks < 4; ks++) {
                uint32_t off = SWZ((uint32_t)((wid * 16 + lr16) * 128 + ks * 32 + alc));
                ldsm4(qfh[ks], sb + ATT_Q + off);
            }
        }

        const uint32_t sK = sb + ATT_ST + (kt & 1) * ATT_STG;
        const uint32_t sV = sK + 16384;
        const uint32_t sM = sb + ATT_MSK + (kt & 1) * 512;

        float sacc[16][4];
#pragma unroll
        for (int j = 0; j < 16; j++)
#pragma unroll
            for (int e = 0; e < 4; e++) sacc[j][e] = 0.f;

#pragma unroll
        for (int p = 0; p < 8; p++) {
#pragma unroll
            for (int ks = 0; ks < 4; ks++) {
                uint32_t koff = SWZ((uint32_t)((p * 16 + brow) * 128 + ks * 32 + bcol));
                uint32_t kbh[4];
                ldsm4(kbh, sK + koff);
#pragma unroll
                for (int a = 0; a < 2; a++)
                    mma_f16(sacc[p * 2 + a], qfh[ks], &kbh[2 * a]);
            }
        }

        float mx0 = -INFINITY, mx1 = -INFINITY;
#pragma unroll
        for (int j = 0; j < 16; j++) {
            mx0 = fmaxf(mx0, fmaxf(sacc[j][0], sacc[j][1]));
            mx1 = fmaxf(mx1, fmaxf(sacc[j][2], sacc[j][3]));
        }
        mx0 = fmaxf(mx0, __shfl_xor_sync(0xffffffffu, mx0, 1));
        mx0 = fmaxf(mx0, __shfl_xor_sync(0xffffffffu, mx0, 2));
        mx1 = fmaxf(mx1, __shfl_xor_sync(0xffffffffu, mx1, 1));
        mx1 = fmaxf(mx1, __shfl_xor_sync(0xffffffffu, mx1, 2));
        const float mnew0 = fmaxf(mrow0, mx0);
        const float mnew1 = fmaxf(mrow1, mx1);
        const float al0 = __expf(mrow0 - mnew0);
        const float al1 = __expf(mrow1 - mnew1);
        float ls0 = 0.f, ls1 = 0.f;
#pragma unroll
        for (int j = 0; j < 16; j++) {
            float2 mv;
            asm volatile("ld.shared.v2.f32 {%0,%1}, [%2];"
                : "=f"(mv.x), "=f"(mv.y)
                : "r"(sM + (uint32_t)((j * 8 + 2 * (lane & 3)) * 4)));
            float p0 = __expf(sacc[j][0] - mnew0) * mv.x;
            float p1 = __expf(sacc[j][1] - mnew0) * mv.y;
            float p2 = __expf(sacc[j][2] - mnew1) * mv.x;
            float p3 = __expf(sacc[j][3] - mnew1) * mv.y;
            sacc[j][0] = p0; sacc[j][1] = p1; sacc[j][2] = p2; sacc[j][3] = p3;
            ls0 += p0 + p1; ls1 += p2 + p3;
        }
        ls0 += __shfl_xor_sync(0xffffffffu, ls0, 1);
        ls0 += __shfl_xor_sync(0xffffffffu, ls0, 2);
        ls1 += __shfl_xor_sync(0xffffffffu, ls1, 1);
        ls1 += __shfl_xor_sync(0xffffffffu, ls1, 2);
        lsum0 = lsum0 * al0 + ls0;
        lsum1 = lsum1 * al1 + ls1;
        mrow0 = mnew0; mrow1 = mnew1;
#pragma unroll
        for (int q = 0; q < 8; q++) {
            oacc[q][0] *= al0; oacc[q][1] *= al0;
            oacc[q][2] *= al1; oacc[q][3] *= al1;
        }

        // O += P * Vh  (P truncated to fp16)
#pragma unroll
        for (int ks = 0; ks < 8; ks++) {
            uint32_t ph[4];
            {
                const float* s0 = sacc[2 * ks];
                const float* s1 = sacc[2 * ks + 1];
                ph[0] = packh(s0[0], s0[1]); ph[1] = packh(s0[2], s0[3]);
                ph[2] = packh(s1[0], s1[1]); ph[3] = packh(s1[2], s1[3]);
            }
#pragma unroll
            for (int q = 0; q < 4; q++) {
                uint32_t voff = SWZ((uint32_t)((ks * 16 + vrow) * 128 + q * 32 + vcol));
                uint32_t vbh[4];
                ldsm4t(vbh, sV + voff);
#pragma unroll
                for (int a = 0; a < 2; a++)
                    mma_f16(oacc[q * 2 + a], ph, &vbh[2 * a]);
            }
        }
    }

    const float inv0 = 1.f / lsum0;
    const float inv1 = 1.f / lsum1;
    const int tok0 = b * Ss + q0 + wid * 16 + (lane >> 2);
#pragma unroll
    for (int q = 0; q < 8; q++) {
        const int col = h * DH + q * 8 + 2 * (lane & 3);
        *(uint32_t*)(oh + (size_t)tok0 * Dd + col) =
            packh(oacc[q][0] * inv0, oacc[q][1] * inv0);
        *(uint32_t*)(oh + (size_t)(tok0 + 8) * Dd + col) =
            packh(oacc[q][2] * inv1, oacc[q][3] * inv1);
    }
}

// ------------------------------ LayerNorm -----------------------------------
template<bool WB>
__global__ void __launch_bounds__(256) ln_k(
    const float* __restrict__ X, const float* __restrict__ gg,
    const float* __restrict__ bb, float* __restrict__ Y,
    fp16* __restrict__ Yh)
{
    __shared__ float red[16];
    const int row = blockIdx.x, tid = threadIdx.x;
    const float4 x = ((const float4*)(X + (size_t)row * Dd))[tid];
    float s  = x.x + x.y + x.z + x.w;
    float s2 = x.x*x.x + x.y*x.y + x.z*x.z + x.w*x.w;
#pragma unroll
    for (int o = 16; o; o >>= 1) {
        s  += __shfl_xor_sync(0xffffffffu, s,  o);
        s2 += __shfl_xor_sync(0xffffffffu, s2, o);
    }
    const int w = tid >> 5, lane = tid & 31;
    if (lane == 0) { red[w] = s; red[8 + w] = s2; }
    __syncthreads();
    if (tid < 32) {
        float a = (tid < 8) ? red[tid]     : 0.f;
        float c = (tid < 8) ? red[8 + tid] : 0.f;
#pragma unroll
        for (int o = 4; o; o >>= 1) {
            a += __shfl_xor_sync(0xffffffffu, a, o);
            c += __shfl_xor_sync(0xffffffffu, c, o);
        }
        if (tid == 0) { red[0] = a; red[8] = c; }
    }
    __syncthreads();
    const float mean = red[0] * (1.f / Dd);
    const float var  = red[8] * (1.f / Dd) - mean * mean;
    const float rstd = rsqrtf(var + 1e-12f);
    const float4 gv = ((const float4*)gg)[tid];
    const float4 bv = ((const float4*)bb)[tid];
    float4 y;
    y.x = (x.x - mean) * rstd * gv.x + bv.x;
    y.y = (x.y - mean) * rstd * gv.y + bv.y;
    y.z = (x.z - mean) * rstd * gv.z + bv.z;
    y.w = (x.w - mean) * rstd * gv.w + bv.w;
    ((float4*)(Y + (size_t)row * Dd))[tid] = y;
    if (WB) {
        uint2 vh2;
        vh2.x = packh(y.x, y.y);  vh2.y = packh(y.z, y.w);
        ((uint2*)(Yh + (size_t)row * Dd))[tid] = vh2;
    }
}

// -------------------------- fp32 -> fp16 conversions ------------------------
__global__ void __launch_bounds__(256) cvth_k(
    const float* __restrict__ X, fp16* __restrict__ Hc, int n4)
{
    int i = blockIdx.x * 256 + threadIdx.x;
    if (i >= n4) return;
    float4 v = ((const float4*)X)[i];
    uint2 vh2;
    vh2.x = packh(v.x, v.y);  vh2.y = packh(v.z, v.w);
    ((uint2*)Hc)[i] = vh2;
}

__global__ void __launch_bounds__(256) cvt4h_k(int n4)
{
    const int a = blockIdx.y;
    int i = blockIdx.x * 256 + threadIdx.x;
    if (i >= n4) return;
    const float* X = g_cvt_src[a];
    fp16* Hc = g_cvt_dh[a];
    float4 v = ((const float4*)X)[i];
    uint2 vh2;
    vh2.x = packh(v.x, v.y);  vh2.y = packh(v.z, v.w);
    ((uint2*)Hc)[i] = vh2;
}

__global__ void __launch_bounds__(256) maskf_k(const int* __restrict__ m,
                                              float* __restrict__ mfo, int n)
{
    int i = blockIdx.x * 256 + threadIdx.x;
    if (i < n) mfo[i] = (m[i] != 0) ? 1.f : 0.f;
}

// ------------------------------ launch --------------------------------------
extern "C" void kernel_launch(void* const* d_in, const int* in_sizes, int n_in,
                              void* d_out, int out_size)
{
    const float* x    = (const float*)d_in[0];
    const int*   amsk = (const int*)  d_in[1];
    const float* Wq   = (const float*)d_in[2];
    const float* bq   = (const float*)d_in[3];
    const float* Wk   = (const float*)d_in[4];
    const float* bk   = (const float*)d_in[5];
    const float* Wv   = (const float*)d_in[6];
    const float* bv   = (const float*)d_in[7];
    const float* Wo   = (const float*)d_in[8];
    const float* bo   = (const float*)d_in[9];
    const float* ln1g = (const float*)d_in[10];
    const float* ln1b = (const float*)d_in[11];
    const float* W1   = (const float*)d_in[12];
    const float* b1   = (const float*)d_in[13];
    const float* W2   = (const float*)d_in[14];
    const float* b2   = (const float*)d_in[15];
    const float* ln2g = (const float*)d_in[16];
    const float* ln2b = (const float*)d_in[17];
    float* out = (float*)d_out;

    float *sap, *hp, *f2p, *mfp;
    fp16 *xh, *qhp, *khp, *vhp, *cxh, *hhp, *fhp;
    fp16 *wqh, *wkh, *wvh, *woh, *w1h, *w2h;
    cudaGetSymbolAddress((void**)&sap, g_sa);  cudaGetSymbolAddress((void**)&hp,  g_h);
    cudaGetSymbolAddress((void**)&f2p, g_f2);  cudaGetSymbolAddress((void**)&mfp, g_mf);
    cudaGetSymbolAddress((void**)&xh,  g_xh);
    cudaGetSymbolAddress((void**)&qhp, g_qh);
    cudaGetSymbolAddress((void**)&khp, g_kh);  cudaGetSymbolAddress((void**)&vhp, g_vh);
    cudaGetSymbolAddress((void**)&cxh, g_cxh);
    cudaGetSymbolAddress((void**)&hhp, g_hh);
    cudaGetSymbolAddress((void**)&fhp, g_fh);
    cudaGetSymbolAddress((void**)&wqh, g_wqh); cudaGetSymbolAddress((void**)&wkh, g_wkh);
    cudaGetSymbolAddress((void**)&wvh, g_wvh); cudaGetSymbolAddress((void**)&woh, g_woh);
    cudaGetSymbolAddress((void**)&w1h, g_w1h); cudaGetSymbolAddress((void**)&w2h, g_w2h);

    static const float* h_src[4];
    static fp16* h_dh[4];
    h_src[0] = Wq; h_src[1] = Wk; h_src[2] = Wv; h_src[3] = Wo;
    h_dh[0] = wqh; h_dh[1] = wkh; h_dh[2] = wvh; h_dh[3] = woh;
    void *d_src_tab, *d_dh_tab;
    cudaGetSymbolAddress(&d_src_tab, g_cvt_src);
    cudaGetSymbolAddress(&d_dh_tab,  g_cvt_dh);
    cudaMemcpyAsync(d_src_tab, h_src, sizeof(h_src), cudaMemcpyHostToDevice);
    cudaMemcpyAsync(d_dh_tab,  h_dh,  sizeof(h_dh),  cudaMemcpyHostToDevice);

    cudaFuncSetAttribute(gemm_qkv,           cudaFuncAttributeMaxDynamicSharedMemorySize, GEMM_SMEM);
    cudaFuncSetAttribute(gemm_mma<EPI_RES>,  cudaFuncAttributeMaxDynamicSharedMemorySize, GEMM_SMEM);
    cudaFuncSetAttribute(gemm_mma<EPI_GELU>, cudaFuncAttributeMaxDynamicSharedMemorySize, GEMM_SMEM);
    cudaFuncSetAttribute(attn_mma, cudaFuncAttributeMaxDynamicSharedMemorySize, ATT_SMEM);

    dim3 gD(Dd/256, TT/128);    // (4, 64)
    dim3 gF(Ff/256, TT/128);    // (16, 64)

    // Launches: 1 cvt_x, 2 cvt4h(weights), 3 maskf, 4 qkv, 5 attn, 6 O-gemm.
    cvth_k<<<(TT*Dd/4 + 255)/256, 256>>>(x, xh, TT*Dd/4);                       // 1
    cvt4h_k<<<dim3((Dd*Dd/4 + 255)/256, 4), 256>>>(Dd*Dd/4);                    // 2
    maskf_k<<<(Bb*Ss + 255)/256, 256>>>(amsk, mfp, Bb*Ss);                      // 3

    // 4. fused QKV projection
    gemm_qkv<<<dim3(12, TT/128), 256, GEMM_SMEM>>>(xh, wqh, wkh, wvh,
                                                   bq, bk, bv, qhp, khp, vhp);

    // 5. attention -> ctx fp16
    attn_mma<<<dim3(Ss/128, Hh, Bb), 256, ATT_SMEM>>>(qhp, khp, vhp, mfp, cxh);

    // 6. output projection + residual (fp32)
    gemm_mma<EPI_RES><<<gD, 256, GEMM_SMEM>>>(cxh, woh, bo, x,
                                              sap, nullptr, Dd, Dd);

    // 7. LN1 -> fp32 + fp16
    ln_k<true><<<TT, 256>>>(sap, ln1g, ln1b, hp, hhp);

    // 8. cvt W1
    cvth_k<<<(Ff*Dd/4 + 255)/256, 256>>>(W1, w1h, Ff*Dd/4);

    // 9. FFN up + gelu -> fp16
    gemm_mma<EPI_GELU><<<gF, 256, GEMM_SMEM>>>(hhp, w1h, b1, nullptr,
                                               nullptr, fhp, Ff, Dd);

    // 10. cvt W2
    cvth_k<<<(Dd*Ff/4 + 255)/256, 256>>>(W2, w2h, Dd*Ff/4);

    // 11. FFN down + residual (fp32)
    gemm_mma<EPI_RES><<<gD, 256, GEMM_SMEM>>>(fhp, w2h, b2, hp,
                                              f2p, nullptr, Dd, Ff);

    // 12. LN2 -> output
    ln_k<false><<<TT, 256>>>(f2p, ln2g, ln2b, out, nullptr);
}

// round 13
// speedup vs baseline: 2.4390x; 1.5915x over previous
#include <cuda_runtime.h>
#include <cuda_fp16.h>
#include <math.h>
#include <stdint.h>

// ---------------------------------------------------------------------------
// TransformerBlock B=8 S=1024 D=1024 H=16 DH=64 F=4096 (fp32 in/out)
// All matmuls: plain fp16 mma.sync.m16n8k16, fp32 accumulate.
// GEMM: BM=128 BN=128 BK=64, 2-stage cp.async, 2 CTAs/SM (16 warps).
// ---------------------------------------------------------------------------

#define Bb 8
#define Ss 1024
#define Dd 1024
#define Hh 16
#define DH 64
#define Ff 4096
#define TT (Bb*Ss)

typedef __half fp16;

// ------------------------- static device scratch ---------------------------
__device__ float g_sa[TT*Dd];
__device__ float g_h [TT*Dd];
__device__ float g_f2[TT*Dd];
__device__ float g_mf[Bb*Ss];

__device__ fp16 g_xh [TT*Dd];
__device__ fp16 g_qh [TT*Dd];
__device__ fp16 g_kh [TT*Dd];
__device__ fp16 g_vh [TT*Dd];
__device__ fp16 g_cxh[TT*Dd];
__device__ fp16 g_hh [TT*Dd];
__device__ fp16 g_fh [TT*Ff];
__device__ fp16 g_wqh[Dd*Dd];
__device__ fp16 g_wkh[Dd*Dd];
__device__ fp16 g_wvh[Dd*Dd];
__device__ fp16 g_woh[Dd*Dd];
__device__ fp16 g_w1h[Ff*Dd];
__device__ fp16 g_w2h[Dd*Ff];

// pointer table for batched weight conversion (hi only)
__device__ const float* g_cvt_src[4];
__device__ fp16*        g_cvt_dh [4];

// ------------------------------ helpers ------------------------------------
__device__ __forceinline__ uint32_t smem_u32(const void* p) {
    uint32_t a;
    asm("{ .reg .u64 t; cvta.to.shared.u64 t, %1; cvt.u32.u64 %0, t; }"
        : "=r"(a) : "l"(p));
    return a;
}
__device__ __forceinline__ void cp16(uint32_t s, const void* g) {
    asm volatile("cp.async.cg.shared.global [%0], [%1], 16;" :: "r"(s), "l"(g));
}
#define CP_COMMIT() asm volatile("cp.async.commit_group;" ::: "memory")
#define CP_WAIT0()  asm volatile("cp.async.wait_group 0;" ::: "memory")

#define SWZ(x)   ((x) ^ (((x) >> 3) & 0x70))   // 128B rows

__device__ __forceinline__ void ldsm4(uint32_t* r, uint32_t a) {
    asm volatile("ldmatrix.sync.aligned.m8n8.x4.shared.b16 {%0,%1,%2,%3}, [%4];"
        : "=r"(r[0]), "=r"(r[1]), "=r"(r[2]), "=r"(r[3]) : "r"(a));
}
__device__ __forceinline__ void ldsm4t(uint32_t* r, uint32_t a) {
    asm volatile("ldmatrix.sync.aligned.m8n8.x4.trans.shared.b16 {%0,%1,%2,%3}, [%4];"
        : "=r"(r[0]), "=r"(r[1]), "=r"(r[2]), "=r"(r[3]) : "r"(a));
}
__device__ __forceinline__ void mma_f16(float* d, const uint32_t* a, const uint32_t* b) {
    asm volatile(
        "mma.sync.aligned.m16n8k16.row.col.f32.f16.f16.f32 "
        "{%0,%1,%2,%3}, {%4,%5,%6,%7}, {%8,%9}, {%0,%1,%2,%3};"
        : "+f"(d[0]), "+f"(d[1]), "+f"(d[2]), "+f"(d[3])
        : "r"(a[0]), "r"(a[1]), "r"(a[2]), "r"(a[3]), "r"(b[0]), "r"(b[1]));
}
__device__ __forceinline__ uint32_t packh(float a, float b) {
    __half2 t = __floats2half2_rn(a, b);
    return reinterpret_cast<uint32_t&>(t);
}
__device__ __forceinline__ float gelu_exact(float v) {
    return 0.5f * v * (1.0f + erff(v * 0.70710678118654752440f));
}

// ----------------------------- GEMM core -----------------------------------
// stage: A 16K | W 16K = 32K; two stages = 64K smem -> 2 CTAs/SM.
#define GSTG 32768
#define GEMM_SMEM (2*GSTG)

#define EPI_RES   1
#define EPI_GELU  2

// BM=128 BN=128 BK=64. 8 warps (2x4), warp tile 64x32 (4 m-atoms x 4 n-atoms).
template<typename ACC>
__device__ __forceinline__ void gemm_mainloop(
    uint32_t sb, int tid, int lane, int wr, int wc,
    const fp16* A_h, const fp16* W_h,
    int m0, int n0, int K, ACC& acc)
{
    auto load_stage = [&](int st, int kt) {
        const uint32_t s0 = sb + st * GSTG;
        const int k0 = kt * 64;
#pragma unroll
        for (int t = 0; t < 4; t++) {         // A: 128 rows x 128B
            int idx = t * 256 + tid;
            int row = idx >> 3, c = idx & 7;
            uint32_t off = SWZ((uint32_t)(row * 128 + c * 16));
            size_t go = (size_t)(m0 + row) * K + k0 + c * 8;
            cp16(s0 + off, A_h + go);
        }
#pragma unroll
        for (int t = 0; t < 4; t++) {         // W: 128 rows x 128B
            int idx = t * 256 + tid;
            int row = idx >> 3, c = idx & 7;
            uint32_t off = SWZ((uint32_t)(row * 128 + c * 16));
            size_t go = (size_t)(n0 + row) * K + k0 + c * 8;
            cp16(s0 + 16384 + off, W_h + go);
        }
    };

    const int KT = K >> 6;
    load_stage(0, 0);
    CP_COMMIT();

    const int lr16 = lane & 15;
    const int alc  = (lane >> 4) * 16;
    const int brow = wc * 32 + (lane & 7) + ((lane >> 4) & 1) * 8;
    const int bcol = ((lane >> 3) & 1) * 16;

    for (int kt = 0; kt < KT; kt++) {
        CP_WAIT0();
        __syncthreads();
        if (kt + 1 < KT) { load_stage((kt + 1) & 1, kt + 1); CP_COMMIT(); }

        const uint32_t sA = sb + (kt & 1) * GSTG;
        const uint32_t sB = sA + 16384;

#pragma unroll
        for (int ks = 0; ks < 4; ks++) {
            uint32_t ah[4][4];
#pragma unroll
            for (int i = 0; i < 4; i++) {
                uint32_t off = SWZ((uint32_t)((wr * 64 + i * 16 + lr16) * 128 + ks * 32 + alc));
                ldsm4(ah[i], sA + off);
            }
#pragma unroll
            for (int p = 0; p < 2; p++) {
                uint32_t boff = SWZ((uint32_t)((brow + p * 16) * 128 + ks * 32 + bcol));
                uint32_t bh[4];
                ldsm4(bh, sB + boff);
#pragma unroll
                for (int a = 0; a < 2; a++) {
#pragma unroll
                    for (int i = 0; i < 4; i++)
                        mma_f16(acc[i][p * 2 + a], ah[i], &bh[2 * a]);
                }
            }
        }
    }
}

// fused QKV projection: grid (24, 64); blockIdx.x>>3 selects Q/K/V
__global__ void __launch_bounds__(256, 2) gemm_qkv(
    const fp16* __restrict__ xh,
    const fp16* __restrict__ wqh, const fp16* __restrict__ wkh,
    const fp16* __restrict__ wvh,
    const float* __restrict__ bq, const float* __restrict__ bk,
    const float* __restrict__ bv,
    fp16* __restrict__ qh, fp16* __restrict__ kh, fp16* __restrict__ vh)
{
    extern __shared__ char smem[];
    const uint32_t sb = smem_u32(smem);
    const int tid = threadIdx.x;
    const int lane = tid & 31, wid = tid >> 5;
    const int wr = wid >> 2, wc = wid & 3;
    const int mat = blockIdx.x >> 3;
    const int n0 = (blockIdx.x & 7) * 128;
    const int m0 = blockIdx.y * 128;

    const fp16* W_h = (mat == 0) ? wqh : (mat == 1) ? wkh : wvh;
    const float* bias = (mat == 0) ? bq : (mat == 1) ? bk : bv;
    fp16* Ch = (mat == 0) ? qh : (mat == 1) ? kh : vh;
    const float scale = (mat == 0) ? 0.125f : 1.0f;

    float acc[4][4][4];
#pragma unroll
    for (int i = 0; i < 4; i++)
#pragma unroll
        for (int j = 0; j < 4; j++)
#pragma unroll
            for (int e = 0; e < 4; e++) acc[i][j][e] = 0.f;

    gemm_mainloop(sb, tid, lane, wr, wc, xh, W_h, m0, n0, Dd, acc);

#pragma unroll
    for (int i = 0; i < 4; i++) {
        const int r0 = m0 + wr * 64 + i * 16 + (lane >> 2);
#pragma unroll
        for (int j = 0; j < 4; j++) {
            const int n = n0 + wc * 32 + j * 8 + 2 * (lane & 3);
            const float2 b2 = *(const float2*)&bias[n];
#pragma unroll
            for (int hf = 0; hf < 2; hf++) {
                const int m = r0 + hf * 8;
                float v0 = (acc[i][j][hf * 2 + 0] + b2.x) * scale;
                float v1 = (acc[i][j][hf * 2 + 1] + b2.y) * scale;
                const size_t o = (((size_t)(m >> 10) * Hh + (n >> 6)) * Ss + (m & 1023)) * DH + (n & 63);
                *(uint32_t*)(Ch + o) = packh(v0, v1);
            }
        }
    }
}

template<int EPI>
__global__ void __launch_bounds__(256, 2) gemm_mma(
    const fp16* __restrict__ A_h, const fp16* __restrict__ W_h,
    const float* __restrict__ bias, const float* __restrict__ res,
    float* __restrict__ Cf, fp16* __restrict__ Ch,
    int N, int K)
{
    extern __shared__ char smem[];
    const uint32_t sb = smem_u32(smem);
    const int tid = threadIdx.x;
    const int lane = tid & 31, wid = tid >> 5;
    const int wr = wid >> 2, wc = wid & 3;
    const int m0 = blockIdx.y * 128, n0 = blockIdx.x * 128;

    float acc[4][4][4];
#pragma unroll
    for (int i = 0; i < 4; i++)
#pragma unroll
        for (int j = 0; j < 4; j++)
#pragma unroll
            for (int e = 0; e < 4; e++) acc[i][j][e] = 0.f;

    gemm_mainloop(sb, tid, lane, wr, wc, A_h, W_h, m0, n0, K, acc);

#pragma unroll
    for (int i = 0; i < 4; i++) {
        const int r0 = m0 + wr * 64 + i * 16 + (lane >> 2);
#pragma unroll
        for (int j = 0; j < 4; j++) {
            const int n = n0 + wc * 32 + j * 8 + 2 * (lane & 3);
            const float2 b2 = *(const float2*)&bias[n];
#pragma unroll
            for (int hf = 0; hf < 2; hf++) {
                const int m = r0 + hf * 8;
                float v0 = acc[i][j][hf * 2 + 0] + b2.x;
                float v1 = acc[i][j][hf * 2 + 1] + b2.y;
                if (EPI == EPI_RES) {
                    const size_t o = (size_t)m * N + n;
                    const float2 rr = *(const float2*)&res[o];
                    float2 w; w.x = v0 + rr.x; w.y = v1 + rr.y;
                    *(float2*)&Cf[o] = w;
                } else { // EPI_GELU -> fp16
                    const size_t o = (size_t)m * N + n;
                    *(uint32_t*)(Ch + o) = packh(gelu_exact(v0), gelu_exact(v1));
                }
            }
        }
    }
}

// --------------------------- flash attention (mma) --------------------------
// Q 16K | stage{Kh 16K, Vh 16K} x2 | mask 2x512B   (unchanged from R12)
#define ATT_Q   0
#define ATT_ST  16384
#define ATT_STG 32768
#define ATT_MSK (ATT_ST + 2*ATT_STG)
#define ATT_SMEM (ATT_MSK + 1024)

__global__ void __launch_bounds__(256) attn_mma(
    const fp16* __restrict__ qh, const fp16* __restrict__ kh,
    const fp16* __restrict__ vh,
    const float* __restrict__ mf,
    fp16* __restrict__ oh)
{
    extern __shared__ char smem[];
    const uint32_t sb = smem_u32(smem);
    const int tid = threadIdx.x;
    const int lane = tid & 31, wid = tid >> 5;
    const int b = blockIdx.z, h = blockIdx.y, q0 = blockIdx.x * 128;

    const size_t bh_off = ((size_t)(b * Hh + h) * Ss) * DH;
    const fp16* qhp = qh + bh_off + (size_t)q0 * DH;
    const fp16* khp = kh + bh_off;
    const fp16* vhp = vh + bh_off;
    const float* mfb = mf + b * Ss;

    auto load_kv = [&](int st, int kt) {
        const uint32_t s0 = sb + ATT_ST + st * ATT_STG;
        const int kv0 = kt * 128;
#pragma unroll
        for (int t = 0; t < 4; t++) {
            int idx = t * 256 + tid;
            int row = idx >> 3, c = idx & 7;
            uint32_t off = SWZ((uint32_t)(row * 128 + c * 16));
            size_t go = (size_t)(kv0 + row) * DH + c * 8;
            cp16(s0 + off,         khp + go);
            cp16(s0 + 16384 + off, vhp + go);
        }
        if (tid < 32) cp16(sb + ATT_MSK + st * 512 + tid * 16, mfb + kv0 + tid * 4);
    };

    {
#pragma unroll
        for (int t = 0; t < 4; t++) {
            int idx = t * 256 + tid;
            int row = idx >> 3, c = idx & 7;
            uint32_t off = SWZ((uint32_t)(row * 128 + c * 16));
            size_t go = (size_t)row * DH + c * 8;
            cp16(sb + ATT_Q + off, qhp + go);
        }
        load_kv(0, 0);
        CP_COMMIT();
    }

    uint32_t qfh[4][4];
    float oacc[8][4];
#pragma unroll
    for (int q = 0; q < 8; q++)
#pragma unroll
        for (int e = 0; e < 4; e++) oacc[q][e] = 0.f;
    float mrow0 = -INFINITY, mrow1 = -INFINITY, lsum0 = 0.f, lsum1 = 0.f;

    const int lr16 = lane & 15;
    const int alc  = (lane >> 4) * 16;
    const int brow = (lane & 7) + ((lane >> 4) & 1) * 8;
    const int bcol = ((lane >> 3) & 1) * 16;
    const int vrow = (lane & 7) + ((lane >> 3) & 1) * 8;
    const int vcol = (lane >> 4) * 16;

    const int NKV = Ss / 128;
    for (int kt = 0; kt < NKV; kt++) {
        CP_WAIT0();
        __syncthreads();
        if (kt + 1 < NKV) { load_kv((kt + 1) & 1, kt + 1); CP_COMMIT(); }

        if (kt == 0) {
#pragma unroll
            for (int ks = 0; ks < 4; ks++) {
                uint32_t off = SWZ((uint32_t)((wid * 16 + lr16) * 128 + ks * 32 + alc));
                ldsm4(qfh[ks], sb + ATT_Q + off);
            }
        }

        const uint32_t sK = sb + ATT_ST + (kt & 1) * ATT_STG;
        const uint32_t sV = sK + 16384;
        const uint32_t sM = sb + ATT_MSK + (kt & 1) * 512;

        float sacc[16][4];
#pragma unroll
        for (int j = 0; j < 16; j++)
#pragma unroll
            for (int e = 0; e < 4; e++) sacc[j][e] = 0.f;

#pragma unroll
        for (int p = 0; p < 8; p++) {
#pragma unroll
            for (int ks = 0; ks < 4; ks++) {
                uint32_t koff = SWZ((uint32_t)((p * 16 + brow) * 128 + ks * 32 + bcol));
                uint32_t kbh[4];
                ldsm4(kbh, sK + koff);
#pragma unroll
                for (int a = 0; a < 2; a++)
                    mma_f16(sacc[p * 2 + a], qfh[ks], &kbh[2 * a]);
            }
        }

        float mx0 = -INFINITY, mx1 = -INFINITY;
#pragma unroll
        for (int j = 0; j < 16; j++) {
            mx0 = fmaxf(mx0, fmaxf(sacc[j][0], sacc[j][1]));
            mx1 = fmaxf(mx1, fmaxf(sacc[j][2], sacc[j][3]));
        }
        mx0 = fmaxf(mx0, __shfl_xor_sync(0xffffffffu, mx0, 1));
        mx0 = fmaxf(mx0, __shfl_xor_sync(0xffffffffu, mx0, 2));
        mx1 = fmaxf(mx1, __shfl_xor_sync(0xffffffffu, mx1, 1));
        mx1 = fmaxf(mx1, __shfl_xor_sync(0xffffffffu, mx1, 2));
        const float mnew0 = fmaxf(mrow0, mx0);
        const float mnew1 = fmaxf(mrow1, mx1);
        const float al0 = __expf(mrow0 - mnew0);
        const float al1 = __expf(mrow1 - mnew1);
        float ls0 = 0.f, ls1 = 0.f;
#pragma unroll
        for (int j = 0; j < 16; j++) {
            float2 mv;
            asm volatile("ld.shared.v2.f32 {%0,%1}, [%2];"
                : "=f"(mv.x), "=f"(mv.y)
                : "r"(sM + (uint32_t)((j * 8 + 2 * (lane & 3)) * 4)));
            float p0 = __expf(sacc[j][0] - mnew0) * mv.x;
            float p1 = __expf(sacc[j][1] - mnew0) * mv.y;
            float p2 = __expf(sacc[j][2] - mnew1) * mv.x;
            float p3 = __expf(sacc[j][3] - mnew1) * mv.y;
            sacc[j][0] = p0; sacc[j][1] = p1; sacc[j][2] = p2; sacc[j][3] = p3;
            ls0 += p0 + p1; ls1 += p2 + p3;
        }
        ls0 += __shfl_xor_sync(0xffffffffu, ls0, 1);
        ls0 += __shfl_xor_sync(0xffffffffu, ls0, 2);
        ls1 += __shfl_xor_sync(0xffffffffu, ls1, 1);
        ls1 += __shfl_xor_sync(0xffffffffu, ls1, 2);
        lsum0 = lsum0 * al0 + ls0;
        lsum1 = lsum1 * al1 + ls1;
        mrow0 = mnew0; mrow1 = mnew1;
#pragma unroll
        for (int q = 0; q < 8; q++) {
            oacc[q][0] *= al0; oacc[q][1] *= al0;
            oacc[q][2] *= al1; oacc[q][3] *= al1;
        }

#pragma unroll
        for (int ks = 0; ks < 8; ks++) {
            uint32_t ph[4];
            {
                const float* s0 = sacc[2 * ks];
                const float* s1 = sacc[2 * ks + 1];
                ph[0] = packh(s0[0], s0[1]); ph[1] = packh(s0[2], s0[3]);
                ph[2] = packh(s1[0], s1[1]); ph[3] = packh(s1[2], s1[3]);
            }
#pragma unroll
            for (int q = 0; q < 4; q++) {
                uint32_t voff = SWZ((uint32_t)((ks * 16 + vrow) * 128 + q * 32 + vcol));
                uint32_t vbh[4];
                ldsm4t(vbh, sV + voff);
#pragma unroll
                for (int a = 0; a < 2; a++)
                    mma_f16(oacc[q * 2 + a], ph, &vbh[2 * a]);
            }
        }
    }

    const float inv0 = 1.f / lsum0;
    const float inv1 = 1.f / lsum1;
    const int tok0 = b * Ss + q0 + wid * 16 + (lane >> 2);
#pragma unroll
    for (int q = 0; q < 8; q++) {
        const int col = h * DH + q * 8 + 2 * (lane & 3);
        *(uint32_t*)(oh + (size_t)tok0 * Dd + col) =
            packh(oacc[q][0] * inv0, oacc[q][1] * inv0);
        *(uint32_t*)(oh + (size_t)(tok0 + 8) * Dd + col) =
            packh(oacc[q][2] * inv1, oacc[q][3] * inv1);
    }
}

// ------------------------------ LayerNorm -----------------------------------
template<bool WB>
__global__ void __launch_bounds__(256) ln_k(
    const float* __restrict__ X, const float* __restrict__ gg,
    const float* __restrict__ bb, float* __restrict__ Y,
    fp16* __restrict__ Yh)
{
    __shared__ float red[16];
    const int row = blockIdx.x, tid = threadIdx.x;
    const float4 x = ((const float4*)(X + (size_t)row * Dd))[tid];
    float s  = x.x + x.y + x.z + x.w;
    float s2 = x.x*x.x + x.y*x.y + x.z*x.z + x.w*x.w;
#pragma unroll
    for (int o = 16; o; o >>= 1) {
        s  += __shfl_xor_sync(0xffffffffu, s,  o);
        s2 += __shfl_xor_sync(0xffffffffu, s2, o);
    }
    const int w = tid >> 5, lane = tid & 31;
    if (lane == 0) { red[w] = s; red[8 + w] = s2; }
    __syncthreads();
    if (tid < 32) {
        float a = (tid < 8) ? red[tid]     : 0.f;
        float c = (tid < 8) ? red[8 + tid] : 0.f;
#pragma unroll
        for (int o = 4; o; o >>= 1) {
            a += __shfl_xor_sync(0xffffffffu, a, o);
            c += __shfl_xor_sync(0xffffffffu, c, o);
        }
        if (tid == 0) { red[0] = a; red[8] = c; }
    }
    __syncthreads();
    const float mean = red[0] * (1.f / Dd);
    const float var  = red[8] * (1.f / Dd) - mean * mean;
    const float rstd = rsqrtf(var + 1e-12f);
    const float4 gv = ((const float4*)gg)[tid];
    const float4 bv = ((const float4*)bb)[tid];
    float4 y;
    y.x = (x.x - mean) * rstd * gv.x + bv.x;
    y.y = (x.y - mean) * rstd * gv.y + bv.y;
    y.z = (x.z - mean) * rstd * gv.z + bv.z;
    y.w = (x.w - mean) * rstd * gv.w + bv.w;
    ((float4*)(Y + (size_t)row * Dd))[tid] = y;
    if (WB) {
        uint2 vh2;
        vh2.x = packh(y.x, y.y);  vh2.y = packh(y.z, y.w);
        ((uint2*)(Yh + (size_t)row * Dd))[tid] = vh2;
    }
}

// -------------------------- fp32 -> fp16 conversions ------------------------
__global__ void __launch_bounds__(256) cvth_k(
    const float* __restrict__ X, fp16* __restrict__ Hc, int n4)
{
    int i = blockIdx.x * 256 + threadIdx.x;
    if (i >= n4) return;
    float4 v = ((const float4*)X)[i];
    uint2 vh2;
    vh2.x = packh(v.x, v.y);  vh2.y = packh(v.z, v.w);
    ((uint2*)Hc)[i] = vh2;
}

__global__ void __launch_bounds__(256) cvt4h_k(int n4)
{
    const int a = blockIdx.y;
    int i = blockIdx.x * 256 + threadIdx.x;
    if (i >= n4) return;
    const float* X = g_cvt_src[a];
    fp16* Hc = g_cvt_dh[a];
    float4 v = ((const float4*)X)[i];
    uint2 vh2;
    vh2.x = packh(v.x, v.y);  vh2.y = packh(v.z, v.w);
    ((uint2*)Hc)[i] = vh2;
}

__global__ void __launch_bounds__(256) maskf_k(const int* __restrict__ m,
                                              float* __restrict__ mfo, int n)
{
    int i = blockIdx.x * 256 + threadIdx.x;
    if (i < n) mfo[i] = (m[i] != 0) ? 1.f : 0.f;
}

// ------------------------------ launch --------------------------------------
extern "C" void kernel_launch(void* const* d_in, const int* in_sizes, int n_in,
                              void* d_out, int out_size)
{
    const float* x    = (const float*)d_in[0];
    const int*   amsk = (const int*)  d_in[1];
    const float* Wq   = (const float*)d_in[2];
    const float* bq   = (const float*)d_in[3];
    const float* Wk   = (const float*)d_in[4];
    const float* bk   = (const float*)d_in[5];
    const float* Wv   = (const float*)d_in[6];
    const float* bv   = (const float*)d_in[7];
    const float* Wo   = (const float*)d_in[8];
    const float* bo   = (const float*)d_in[9];
    const float* ln1g = (const float*)d_in[10];
    const float* ln1b = (const float*)d_in[11];
    const float* W1   = (const float*)d_in[12];
    const float* b1   = (const float*)d_in[13];
    const float* W2   = (const float*)d_in[14];
    const float* b2   = (const float*)d_in[15];
    const float* ln2g = (const float*)d_in[16];
    const float* ln2b = (const float*)d_in[17];
    float* out = (float*)d_out;

    float *sap, *hp, *f2p, *mfp;
    fp16 *xh, *qhp, *khp, *vhp, *cxh, *hhp, *fhp;
    fp16 *wqh, *wkh, *wvh, *woh, *w1h, *w2h;
    cudaGetSymbolAddress((void**)&sap, g_sa);  cudaGetSymbolAddress((void**)&hp,  g_h);
    cudaGetSymbolAddress((void**)&f2p, g_f2);  cudaGetSymbolAddress((void**)&mfp, g_mf);
    cudaGetSymbolAddress((void**)&xh,  g_xh);
    cudaGetSymbolAddress((void**)&qhp, g_qh);
    cudaGetSymbolAddress((void**)&khp, g_kh);  cudaGetSymbolAddress((void**)&vhp, g_vh);
    cudaGetSymbolAddress((void**)&cxh, g_cxh);
    cudaGetSymbolAddress((void**)&hhp, g_hh);
    cudaGetSymbolAddress((void**)&fhp, g_fh);
    cudaGetSymbolAddress((void**)&wqh, g_wqh); cudaGetSymbolAddress((void**)&wkh, g_wkh);
    cudaGetSymbolAddress((void**)&wvh, g_wvh); cudaGetSymbolAddress((void**)&woh, g_woh);
    cudaGetSymbolAddress((void**)&w1h, g_w1h); cudaGetSymbolAddress((void**)&w2h, g_w2h);

    static const float* h_src[4];
    static fp16* h_dh[4];
    h_src[0] = Wq; h_src[1] = Wk; h_src[2] = Wv; h_src[3] = Wo;
    h_dh[0] = wqh; h_dh[1] = wkh; h_dh[2] = wvh; h_dh[3] = woh;
    void *d_src_tab, *d_dh_tab;
    cudaGetSymbolAddress(&d_src_tab, g_cvt_src);
    cudaGetSymbolAddress(&d_dh_tab,  g_cvt_dh);
    cudaMemcpyAsync(d_src_tab, h_src, sizeof(h_src), cudaMemcpyHostToDevice);
    cudaMemcpyAsync(d_dh_tab,  h_dh,  sizeof(h_dh),  cudaMemcpyHostToDevice);

    cudaFuncSetAttribute(gemm_qkv,           cudaFuncAttributeMaxDynamicSharedMemorySize, GEMM_SMEM);
    cudaFuncSetAttribute(gemm_mma<EPI_RES>,  cudaFuncAttributeMaxDynamicSharedMemorySize, GEMM_SMEM);
    cudaFuncSetAttribute(gemm_mma<EPI_GELU>, cudaFuncAttributeMaxDynamicSharedMemorySize, GEMM_SMEM);
    cudaFuncSetAttribute(attn_mma, cudaFuncAttributeMaxDynamicSharedMemorySize, ATT_SMEM);

    dim3 gD(Dd/128, TT/128);    // (8, 64)
    dim3 gF(Ff/128, TT/128);    // (32, 64)

    // Launches: 1 cvt_x, 2 cvt4h(weights), 3 maskf, 4 qkv, 5 attn, 6 O-gemm.
    cvth_k<<<(TT*Dd/4 + 255)/256, 256>>>(x, xh, TT*Dd/4);                       // 1
    cvt4h_k<<<dim3((Dd*Dd/4 + 255)/256, 4), 256>>>(Dd*Dd/4);                    // 2
    maskf_k<<<(Bb*Ss + 255)/256, 256>>>(amsk, mfp, Bb*Ss);                      // 3

    // 4. fused QKV projection
    gemm_qkv<<<dim3(24, TT/128), 256, GEMM_SMEM>>>(xh, wqh, wkh, wvh,
                                                   bq, bk, bv, qhp, khp, vhp);

    // 5. attention -> ctx fp16
    attn_mma<<<dim3(Ss/128, Hh, Bb), 256, ATT_SMEM>>>(qhp, khp, vhp, mfp, cxh);

    // 6. output projection + residual (fp32)
    gemm_mma<EPI_RES><<<gD, 256, GEMM_SMEM>>>(cxh, woh, bo, x,
                                              sap, nullptr, Dd, Dd);

    // 7. LN1 -> fp32 + fp16
    ln_k<true><<<TT, 256>>>(sap, ln1g, ln1b, hp, hhp);

    // 8. cvt W1
    cvth_k<<<(Ff*Dd/4 + 255)/256, 256>>>(W1, w1h, Ff*Dd/4);

    // 9. FFN up + gelu -> fp16
    gemm_mma<EPI_GELU><<<gF, 256, GEMM_SMEM>>>(hhp, w1h, b1, nullptr,
                                               nullptr, fhp, Ff, Dd);

    // 10. cvt W2
    cvth_k<<<(Dd*Ff/4 + 255)/256, 256>>>(W2, w2h, Dd*Ff/4);

    // 11. FFN down + residual (fp32)
    gemm_mma<EPI_RES><<<gD, 256, GEMM_SMEM>>>(fhp, w2h, b2, hp,
                                              f2p, nullptr, Dd, Ff);

    // 12. LN2 -> output
    ln_k<false><<<TT, 256>>>(f2p, ln2g, ln2b, out, nullptr);
}